// round 8
// baseline (speedup 1.0000x reference)
#include <cuda_runtime.h>
#include <cuda_bf16.h>
#include <cstdint>
#include <math.h>

// ---------------- scratch (static device globals; no runtime alloc) ----------
__device__ float g_qkv[2 * 2048 * 3072];        // [B,N,3C] fp32
__device__ float g_vsum[32 * 64];
__device__ float g_vsum_p[32 * 16 * 64];
__device__ __nv_bfloat16 g_xh[4096 * 1024], g_xl[4096 * 1024];
__device__ __nv_bfloat16 g_w1h[3072 * 1024], g_w1l[3072 * 1024];
__device__ __nv_bfloat16 g_w2h[1024 * 1024], g_w2l[1024 * 1024];
__device__ __nv_bfloat16 g_ah[4096 * 1024], g_al[4096 * 1024];
__device__ int g_tc_ok;

// ---------------- helpers -----------------------------------------------------
__device__ __forceinline__ unsigned short bfbits(__nv_bfloat16 v) {
    return *reinterpret_cast<unsigned short*>(&v);
}

// ---------------- fp32 -> bf16 hi/lo split -----------------------------------
__global__ void split_kernel(const float* __restrict__ src,
                             __nv_bfloat16* __restrict__ hi,
                             __nv_bfloat16* __restrict__ lo, int n4) {
    int i = blockIdx.x * 256 + threadIdx.x;
    if (i >= n4) return;
    float4 v = reinterpret_cast<const float4*>(src)[i];
    float vv[4] = {v.x, v.y, v.z, v.w};
    unsigned short hb[4], lb[4];
    #pragma unroll
    for (int j = 0; j < 4; j++) {
        __nv_bfloat16 h = __float2bfloat16_rn(vv[j]);
        __nv_bfloat16 l = __float2bfloat16_rn(vv[j] - __bfloat162float(h));
        hb[j] = bfbits(h); lb[j] = bfbits(l);
    }
    reinterpret_cast<ushort4*>(hi)[i] = make_ushort4(hb[0], hb[1], hb[2], hb[3]);
    reinterpret_cast<ushort4*>(lo)[i] = make_ushort4(lb[0], lb[1], lb[2], lb[3]);
}

// =============================================================================
// Path A: tcgen05 GEMM, (mt*128)x256 tiles, K-chunk 16, SW32, 5-stage ring
// =============================================================================
#define NSTAGE 5
#define A_TILE_B 4096                 // 128 rows * 32 B
#define B_TILE_B 8192                 // 256 rows * 32 B
#define STAGE_MAX (4 * A_TILE_B + 2 * B_TILE_B)   // mt=2: 32 KB
#define GEMM_TC_SMEM (2048 + NSTAGE * STAGE_MAX)  // 165888

#if defined(__CUDA_ARCH__) && defined(__CUDA_ARCH_FEAT_SM103_ALL)
__device__ __forceinline__ uint32_t elect1() {
    uint32_t p;
    asm volatile("{\n\t.reg .pred p;\n\telect.sync _|p, 0xFFFFFFFF;\n\tselp.b32 %0,1,0,p;\n\t}"
                 : "=r"(p));
    return p;
}
__device__ __forceinline__ uint64_t make_desc_sw32(uint32_t addr) {
    // layout=SW32(6), version=1, SBO=16 (8 rows * 32 B), LBO=1
    return ((uint64_t)6 << 61) | ((uint64_t)1 << 46) | ((uint64_t)16 << 32) |
           ((uint64_t)1 << 16) | (uint64_t)((addr >> 4) & 0x3FFF);
}
__device__ __forceinline__ void mma_f16_ss(uint32_t d, uint64_t a, uint64_t b,
                                           uint32_t idesc, uint32_t acc) {
    asm volatile(
        "{\n\t.reg .pred p;\n\tsetp.ne.u32 p, %4, 0;\n\t"
        "tcgen05.mma.cta_group::1.kind::f16 [%0], %1, %2, %3, {%5,%5,%5,%5}, p;\n\t}"
        :: "r"(d), "l"(a), "l"(b), "r"(idesc), "r"(acc), "r"(0u) : "memory");
}
#define MBAR_INIT(a, c) \
    asm volatile("mbarrier.init.shared.b64 [%0], %1;" :: "r"(a), "r"(c) : "memory")
#define MBAR_WAIT(a, ph) do {                                                   \
    uint32_t _done = 0;                                                         \
    while (!_done) {                                                            \
        asm volatile(                                                           \
            "{\n\t.reg .pred p;\n\t"                                            \
            "mbarrier.try_wait.parity.acquire.cta.shared::cta.b64 p, [%1], %2, 0x989680;\n\t" \
            "selp.b32 %0,1,0,p;\n\t}"                                           \
            : "=r"(_done) : "r"(a), "r"((uint32_t)(ph)) : "memory");            \
    }                                                                           \
} while (0)
#define TC_COMMIT(mb) \
    asm volatile("tcgen05.commit.cta_group::1.mbarrier::arrive::one.shared::cluster.b64 [%0];" \
                 :: "r"(mb) : "memory")
#define TC_LD_X32(r, addr)                                                      \
    asm volatile("tcgen05.ld.sync.aligned.32x32b.x32.b32 "                      \
        "{%0,%1,%2,%3,%4,%5,%6,%7,%8,%9,%10,%11,%12,%13,%14,%15,"              \
        "%16,%17,%18,%19,%20,%21,%22,%23,%24,%25,%26,%27,%28,%29,%30,%31}, [%32];" \
        : "=r"((r)[0]),"=r"((r)[1]),"=r"((r)[2]),"=r"((r)[3]),                  \
          "=r"((r)[4]),"=r"((r)[5]),"=r"((r)[6]),"=r"((r)[7]),                  \
          "=r"((r)[8]),"=r"((r)[9]),"=r"((r)[10]),"=r"((r)[11]),                \
          "=r"((r)[12]),"=r"((r)[13]),"=r"((r)[14]),"=r"((r)[15]),              \
          "=r"((r)[16]),"=r"((r)[17]),"=r"((r)[18]),"=r"((r)[19]),              \
          "=r"((r)[20]),"=r"((r)[21]),"=r"((r)[22]),"=r"((r)[23]),              \
          "=r"((r)[24]),"=r"((r)[25]),"=r"((r)[26]),"=r"((r)[27]),              \
          "=r"((r)[28]),"=r"((r)[29]),"=r"((r)[30]),"=r"((r)[31])               \
        : "r"(addr))
#endif

__global__ __launch_bounds__(256, 1)
void gemm_tc(const __nv_bfloat16* __restrict__ Ah_, const __nv_bfloat16* __restrict__ Al_,
             const __nv_bfloat16* __restrict__ Bh_, const __nv_bfloat16* __restrict__ Bl_,
             const float* __restrict__ bias, float* __restrict__ C,
             int N, int K, int mt) {
#if defined(__CUDA_ARCH__) && defined(__CUDA_ARCH_FEAT_SM103_ALL)
    extern __shared__ char smem[];
    const int tid = threadIdx.x;
    const int wid = tid >> 5, lane = tid & 31;
    if (tid == 0) g_tc_ok = 1;
    const int bm = blockIdx.y * (mt * 128), bn = blockIdx.x * 256;
    const uint32_t sbase = (uint32_t)__cvta_generic_to_shared(smem);
    const uint32_t tiles0 = (sbase + 1024 + 1023) & ~1023u;
    const uint32_t mbf0 = sbase + 64, mbd0 = sbase + 192, mbfin = sbase + 320;

    const int nA = mt * 2 * 256;                 // A 16B-units per stage
    const int unitsTot = nA + 1024;              // + B (hi+lo, 512 each)
    const uint32_t stage_b = (uint32_t)nA * 16 + 2 * B_TILE_B;

    if (tid == 0) {
        #pragma unroll
        for (int s = 0; s < NSTAGE; s++) {
            MBAR_INIT(mbf0 + 8 * s, 128);
            MBAR_INIT(mbd0 + 8 * s, 1);
        }
        MBAR_INIT(mbfin, 1);
    }
    if (wid == 0) {
        asm volatile("tcgen05.alloc.cta_group::1.sync.aligned.shared::cta.b32 [%0], %1;"
                     :: "r"(sbase), "r"(512u) : "memory");
    }
    __syncthreads();
    uint32_t tmem;
    asm volatile("ld.shared.b32 %0, [%1];" : "=r"(tmem) : "r"(sbase));

    const int nkt = K >> 4;                 // K/16
    const uint32_t idesc = 0x8400490u;      // f32 d, bf16 a/b, M=128, N=256

    if (wid < 4) {
        // ---------------- producers: 128 threads stream the ring --------------
        const __nv_bfloat16* Asrc[4];
        #pragma unroll
        for (int i = 0; i < 2; i++) {
            Asrc[i * 2 + 0] = Ah_ + (size_t)(bm + i * 128) * K;
            Asrc[i * 2 + 1] = Al_ + (size_t)(bm + i * 128) * K;
        }
        const __nv_bfloat16* Bsrc[2] = { Bh_ + (size_t)bn * K, Bl_ + (size_t)bn * K };

        for (int kt = 0; kt < nkt; kt++) {
            const int s = kt % NSTAGE;
            if (kt >= NSTAGE) {
                MBAR_WAIT(mbd0 + 8 * s, ((kt / NSTAGE) - 1) & 1);
            }
            const uint32_t sb = tiles0 + (uint32_t)s * stage_b;
            const int k0 = kt * 16;
            for (int i = 0; i < 16; i++) {
                const int u = tid + i * 128;
                if (u >= unitsTot) break;
                const __nv_bfloat16* gp;
                uint32_t dst;
                if (u < nA) {                       // A: 256 units per tile
                    const int t = u >> 8, r = (u & 255) >> 1, c = u & 1;
                    uint32_t off = (uint32_t)r * 32 + (uint32_t)c * 16;
                    dst = sb + (uint32_t)t * A_TILE_B + (off ^ ((off >> 3) & 0x10));
                    gp = Asrc[t] + (size_t)r * K + k0 + c * 8;
                } else {                            // B: 512 units per tile
                    const int v = u - nA;
                    const int t = v >> 9, r = (v & 511) >> 1, c = v & 1;
                    uint32_t off = (uint32_t)r * 32 + (uint32_t)c * 16;
                    dst = sb + (uint32_t)nA * 16 + (uint32_t)t * B_TILE_B +
                          (off ^ ((off >> 3) & 0x10));
                    gp = Bsrc[t] + (size_t)r * K + k0 + c * 8;
                }
                asm volatile("cp.async.ca.shared.global [%0], [%1], 16;"
                             :: "r"(dst), "l"(gp));
            }
            asm volatile("cp.async.mbarrier.arrive.noinc.shared::cta.b64 [%0];"
                         :: "r"(mbf0 + 8 * s) : "memory");
        }
    } else if (wid == 4 && elect1()) {
        // ---------------- MMA: one elected thread ----------------------------
        for (int kt = 0; kt < nkt; kt++) {
            const int s = kt % NSTAGE;
            MBAR_WAIT(mbf0 + 8 * s, (kt / NSTAGE) & 1);
            asm volatile("fence.proxy.async.shared::cta;" ::: "memory");
            const uint32_t sb = tiles0 + (uint32_t)s * stage_b;
            const uint64_t dBh = make_desc_sw32(sb + (uint32_t)nA * 16);
            const uint64_t dBl = make_desc_sw32(sb + (uint32_t)nA * 16 + B_TILE_B);
            const uint32_t acc0 = (kt == 0) ? 0u : 1u;
            {
                const uint64_t dAh = make_desc_sw32(sb);
                const uint64_t dAl = make_desc_sw32(sb + A_TILE_B);
                mma_f16_ss(tmem, dAh, dBh, idesc, acc0);
                mma_f16_ss(tmem, dAh, dBl, idesc, 1u);
                mma_f16_ss(tmem, dAl, dBh, idesc, 1u);
            }
            if (mt == 2) {
                const uint64_t dAh = make_desc_sw32(sb + 2 * A_TILE_B);
                const uint64_t dAl = make_desc_sw32(sb + 3 * A_TILE_B);
                mma_f16_ss(tmem + 256, dAh, dBh, idesc, acc0);
                mma_f16_ss(tmem + 256, dAh, dBl, idesc, 1u);
                mma_f16_ss(tmem + 256, dAl, dBh, idesc, 1u);
            }
            TC_COMMIT(mbd0 + 8 * s);
        }
        // final completion marker: single-phase barrier, no parity aliasing
        TC_COMMIT(mbfin);
    }

    MBAR_WAIT(mbfin, 0);
    asm volatile("tcgen05.fence::after_thread_sync;" ::: "memory");
    __syncthreads();

    // ---------------- epilogue -------------------------------------------------
    {
        const int sub = wid >> 2;               // 0..1
        uint32_t dbase; int row, colbase, nG;
        if (mt == 2) {
            dbase = tmem + (uint32_t)sub * 256;
            row = bm + sub * 128 + (wid & 3) * 32 + lane;
            colbase = 0; nG = 8;
        } else {
            dbase = tmem + (uint32_t)sub * 128;
            row = bm + (wid & 3) * 32 + lane;
            colbase = sub * 128; nG = 4;
        }
        float* Cr = C + (size_t)row * N + bn + colbase;
        for (int g = 0; g < nG; g++) {
            uint32_t r[32];
            TC_LD_X32(r, dbase + g * 32);
            asm volatile("tcgen05.wait::ld.sync.aligned;" ::: "memory");
            #pragma unroll
            for (int j = 0; j < 32; j += 4) {
                float4 o;
                o.x = __uint_as_float(r[j + 0]);
                o.y = __uint_as_float(r[j + 1]);
                o.z = __uint_as_float(r[j + 2]);
                o.w = __uint_as_float(r[j + 3]);
                if (bias) {
                    const float4 b4 =
                        *reinterpret_cast<const float4*>(bias + bn + colbase + g * 32 + j);
                    o.x += b4.x; o.y += b4.y; o.z += b4.z; o.w += b4.w;
                }
                *reinterpret_cast<float4*>(Cr + g * 32 + j) = o;
            }
        }
        asm volatile("tcgen05.fence::before_thread_sync;" ::: "memory");
    }
    __syncthreads();
    if (wid == 0) {
        asm volatile("tcgen05.relinquish_alloc_permit.cta_group::1.sync.aligned;");
        asm volatile("tcgen05.dealloc.cta_group::1.sync.aligned.b32 %0, %1;"
                     :: "r"(tmem), "r"(512u));
    }
#endif
}

// =============================================================================
// Path B: fallback — 3xBF16 mma.sync (plain compute_103 safe); skips if A ran
// =============================================================================
#define MSTRIDE 20
#define MTILE_U32 (128 * MSTRIDE)
#define GEMM_MMA_SMEM (8 * MTILE_U32 * 4)

__device__ __forceinline__ void mma_bf16(float* c, const uint32_t* a, const uint32_t* b) {
    asm volatile(
        "mma.sync.aligned.m16n8k16.row.col.f32.bf16.bf16.f32 "
        "{%0,%1,%2,%3}, {%4,%5,%6,%7}, {%8,%9}, {%0,%1,%2,%3};"
        : "+f"(c[0]), "+f"(c[1]), "+f"(c[2]), "+f"(c[3])
        : "r"(a[0]), "r"(a[1]), "r"(a[2]), "r"(a[3]), "r"(b[0]), "r"(b[1]));
}

__global__ __launch_bounds__(256)
void gemm_mma(const __nv_bfloat16* __restrict__ Ah_, const __nv_bfloat16* __restrict__ Al_,
              const __nv_bfloat16* __restrict__ Bh_, const __nv_bfloat16* __restrict__ Bl_,
              const float* __restrict__ bias, float* __restrict__ C, int N, int K) {
    if (*(volatile int*)&g_tc_ok) return;
    extern __shared__ uint32_t sm_u[];

    const int tid = threadIdx.x;
    const int lane = tid & 31;
    const int wid = tid >> 5;
    const int warp_m = wid & 1;
    const int warp_n = wid >> 1;
    const int bm = blockIdx.y * 128;
    const int bn = blockIdx.x * 128;
    const int gr = lane >> 2;
    const int gc = lane & 3;

    const __nv_bfloat16* srcs[4] = {
        Ah_ + (size_t)bm * K, Al_ + (size_t)bm * K,
        Bh_ + (size_t)bn * K, Bl_ + (size_t)bn * K };

    float acc[4][4][4];
    #pragma unroll
    for (int i = 0; i < 4; i++)
        #pragma unroll
        for (int j = 0; j < 4; j++)
            #pragma unroll
            for (int r = 0; r < 4; r++) acc[i][j][r] = 0.0f;

    auto load_stage = [&](int s, int k0) {
        #pragma unroll
        for (int i = 0; i < 8; i++) {
            const int cid = tid + i * 256;
            const int t = cid >> 9;
            const int c = cid & 511;
            const int row = c >> 2, c16 = c & 3;
            uint32_t daddr = (uint32_t)__cvta_generic_to_shared(
                sm_u + (s * 4 + t) * MTILE_U32 + row * MSTRIDE + c16 * 4);
            asm volatile("cp.async.ca.shared.global [%0], [%1], 16;"
                         :: "r"(daddr), "l"(srcs[t] + (size_t)row * K + k0 + c16 * 8));
        }
        asm volatile("cp.async.commit_group;");
    };

    const int nkt = K >> 5;
    load_stage(0, 0);

    for (int kt = 0; kt < nkt; kt++) {
        const int s = kt & 1;
        if (kt + 1 < nkt) {
            load_stage(s ^ 1, (kt + 1) * 32);
            asm volatile("cp.async.wait_group 1;");
        } else {
            asm volatile("cp.async.wait_group 0;");
        }
        __syncthreads();

        const uint32_t* Abh = sm_u + (s * 4 + 0) * MTILE_U32;
        const uint32_t* Abl = sm_u + (s * 4 + 1) * MTILE_U32;
        const uint32_t* Bbh = sm_u + (s * 4 + 2) * MTILE_U32;
        const uint32_t* Bbl = sm_u + (s * 4 + 3) * MTILE_U32;

        #pragma unroll
        for (int ks = 0; ks < 2; ks++) {
            const int kb = ks * 8;
            uint32_t ah[4][4], al[4][4];
            #pragma unroll
            for (int i = 0; i < 4; i++) {
                const int base = (warp_m * 64 + i * 16 + gr) * MSTRIDE + kb + gc;
                ah[i][0] = Abh[base];           ah[i][1] = Abh[base + 8 * MSTRIDE];
                ah[i][2] = Abh[base + 4];       ah[i][3] = Abh[base + 8 * MSTRIDE + 4];
                al[i][0] = Abl[base];           al[i][1] = Abl[base + 8 * MSTRIDE];
                al[i][2] = Abl[base + 4];       al[i][3] = Abl[base + 8 * MSTRIDE + 4];
            }
            uint32_t bh[4][2], bl[4][2];
            #pragma unroll
            for (int j = 0; j < 4; j++) {
                const int bb = (warp_n * 32 + j * 8 + gr) * MSTRIDE + kb + gc;
                bh[j][0] = Bbh[bb];  bh[j][1] = Bbh[bb + 4];
                bl[j][0] = Bbl[bb];  bl[j][1] = Bbl[bb + 4];
            }
            #pragma unroll
            for (int i = 0; i < 4; i++)
                #pragma unroll
                for (int j = 0; j < 4; j++) {
                    mma_bf16(acc[i][j], ah[i], bh[j]);
                    mma_bf16(acc[i][j], ah[i], bl[j]);
                    mma_bf16(acc[i][j], al[i], bh[j]);
                }
        }
        __syncthreads();
    }

    #pragma unroll
    for (int i = 0; i < 4; i++) {
        const int row0 = bm + warp_m * 64 + i * 16 + gr;
        #pragma unroll
        for (int j = 0; j < 4; j++) {
            const int col = bn + warp_n * 32 + j * 8 + gc * 2;
            float2 v0 = make_float2(acc[i][j][0], acc[i][j][1]);
            float2 v1 = make_float2(acc[i][j][2], acc[i][j][3]);
            if (bias) {
                const float b0 = bias[col], b1 = bias[col + 1];
                v0.x += b0; v0.y += b1; v1.x += b0; v1.y += b1;
            }
            *reinterpret_cast<float2*>(C + (size_t)row0 * N + col) = v0;
            *reinterpret_cast<float2*>(C + (size_t)(row0 + 8) * N + col) = v1;
        }
    }
}

// ---------------- V row-sum (2-stage) ----------------------------------------
__global__ void vsum_partial() {
    const int N = 2048, C3 = 3072, Dh = 64, H = 16;
    const int bh = blockIdx.x, s = blockIdx.y;
    const int b = bh / H, h = bh % H;
    const int dh = threadIdx.x;
    const float* base = g_qkv + (size_t)(b * N) * C3 + 2048 + h * Dh + dh;
    float acc = 0.0f;
    const int n0 = s * 128;
    for (int n = n0; n < n0 + 128; n++) acc += base[(size_t)n * C3];
    g_vsum_p[(bh * 16 + s) * Dh + dh] = acc;
}
__global__ void vsum_reduce() {
    const int Dh = 64;
    const int bh = blockIdx.x, dh = threadIdx.x;
    float acc = 0.0f;
    #pragma unroll
    for (int s = 0; s < 16; s++) acc += g_vsum_p[(bh * 16 + s) * Dh + dh];
    g_vsum[bh * Dh + dh] = acc;
}

// ---------------- banded attention: 8 queries/block share K/V rows in smem ---
__global__ __launch_bounds__(256)
void band_attn(const int* __restrict__ epoch_p) {
    const int N = 2048, H = 16, C3 = 3072;
    const int w = (*epoch_p < 15) ? 16 : 20;

    __shared__ float sK[48 * 64];
    __shared__ float sV[48 * 64];

    const int tid = threadIdx.x;
    const int g = blockIdx.x;
    const int n0 = (g & 255) * 8;
    const int bh = g >> 8;
    const int b = bh >> 4, h = bh & 15;

    const int lo = max(0, n0 - w);
    const int hi = min(N - 1, n0 + 7 + w);
    const int rows = hi - lo + 1;

    const float* base = g_qkv + (size_t)(b * N + lo) * C3 + 1024 + h * 64;
    for (int idx = tid; idx < rows * 16; idx += 256) {
        const int r = idx >> 4, c4 = (idx & 15) * 4;
        *reinterpret_cast<float4*>(&sK[r * 64 + c4]) =
            *reinterpret_cast<const float4*>(base + (size_t)r * C3 + c4);
        *reinterpret_cast<float4*>(&sV[r * 64 + c4]) =
            *reinterpret_cast<const float4*>(base + (size_t)r * C3 + 1024 + c4);
    }
    __syncthreads();

    const int wid = tid >> 5, lane = tid & 31;
    const int n = n0 + wid;

    const float* qp = g_qkv + (size_t)(b * N + n) * C3 + h * 64;
    const float q0 = qp[lane], q1 = qp[lane + 32];
    const float s0 = g_vsum[bh * 64 + lane];
    const float s1 = g_vsum[bh * 64 + lane + 32];

    const int m0 = max(0, n - w);
    const int m1 = min(N - 1, n + w);

    float Mx = -INFINITY, Z = 0.0f;
    float a0 = 0.0f, a1 = 0.0f, bv0 = 0.0f, bv1 = 0.0f;

    for (int m = m0; m <= m1; m++) {
        const int r = m - lo;
        const float k0 = sK[r * 64 + lane], k1 = sK[r * 64 + lane + 32];
        const float v0 = sV[r * 64 + lane], v1 = sV[r * 64 + lane + 32];

        float p = q0 * k0 + q1 * k1;
        p += __shfl_xor_sync(0xffffffffu, p, 16);
        p += __shfl_xor_sync(0xffffffffu, p, 8);
        p += __shfl_xor_sync(0xffffffffu, p, 4);
        p += __shfl_xor_sync(0xffffffffu, p, 2);
        p += __shfl_xor_sync(0xffffffffu, p, 1);
        const float l = p * 4.0f;   // scale = Dh // H = 4

        if (l > Mx) {
            const float f = __expf(Mx - l);
            Z *= f; a0 *= f; a1 *= f;
            Mx = l;
        }
        const float e = __expf(l - Mx);
        Z += e;
        a0 = fmaf(e, v0, a0);
        a1 = fmaf(e, v1, a1);
        bv0 += v0; bv1 += v1;
    }

    const float lm = 1e-9f;
    const float cu = __expf(lm - Mx);
    const int nband = m1 - m0 + 1;
    Z += (float)(N - nband) * cu;

    const float invZ = 1.0f / Z;
    const float o0 = (a0 + cu * (s0 - bv0)) * invZ;
    const float o1 = (a1 + cu * (s1 - bv1)) * invZ;

    const size_t idx = (size_t)(b * N + n) * 1024 + h * 64;
    __nv_bfloat16 h0 = __float2bfloat16_rn(o0);
    __nv_bfloat16 l0 = __float2bfloat16_rn(o0 - __bfloat162float(h0));
    __nv_bfloat16 h1 = __float2bfloat16_rn(o1);
    __nv_bfloat16 l1 = __float2bfloat16_rn(o1 - __bfloat162float(h1));
    g_ah[idx + lane] = h0;  g_al[idx + lane] = l0;
    g_ah[idx + lane + 32] = h1;  g_al[idx + lane + 32] = l1;
}

// ---------------- launcher ---------------------------------------------------
extern "C" void kernel_launch(void* const* d_in, const int* in_sizes, int n_in,
                              void* d_out, int out_size) {
    const float* x      = (const float*)d_in[0];
    const float* qkv_w  = (const float*)d_in[1];
    const float* proj_w = (const float*)d_in[2];
    const float* proj_b = (const float*)d_in[3];
    const int*   epoch  = (const int*)d_in[4];

    float* qkv_buf;
    __nv_bfloat16 *xh, *xl, *w1h, *w1l, *w2h, *w2l, *ah, *al;
    cudaGetSymbolAddress((void**)&qkv_buf, g_qkv);
    cudaGetSymbolAddress((void**)&xh, g_xh);   cudaGetSymbolAddress((void**)&xl, g_xl);
    cudaGetSymbolAddress((void**)&w1h, g_w1h); cudaGetSymbolAddress((void**)&w1l, g_w1l);
    cudaGetSymbolAddress((void**)&w2h, g_w2h); cudaGetSymbolAddress((void**)&w2l, g_w2l);
    cudaGetSymbolAddress((void**)&ah, g_ah);   cudaGetSymbolAddress((void**)&al, g_al);

    cudaFuncSetAttribute(gemm_tc, cudaFuncAttributeMaxDynamicSharedMemorySize, GEMM_TC_SMEM);
    cudaFuncSetAttribute(gemm_mma, cudaFuncAttributeMaxDynamicSharedMemorySize, GEMM_MMA_SMEM);

    // 1) split inputs to bf16 hi/lo
    {
        int n4 = 4096 * 1024 / 4;
        split_kernel<<<(n4 + 255) / 256, 256>>>(x, xh, xl, n4);
        n4 = 3072 * 1024 / 4;
        split_kernel<<<(n4 + 255) / 256, 256>>>(qkv_w, w1h, w1l, n4);
        n4 = 1024 * 1024 / 4;
        split_kernel<<<(n4 + 255) / 256, 256>>>(proj_w, w2h, w2l, n4);
    }

    // 2) qkv = x @ qkv_w^T : 256x256 tcgen05 tiles, else fallback
    gemm_tc<<<dim3(3072 / 256, 4096 / 256), 256, GEMM_TC_SMEM>>>(
        xh, xl, w1h, w1l, nullptr, qkv_buf, 3072, 1024, 2);
    gemm_mma<<<dim3(3072 / 128, 4096 / 128), 256, GEMM_MMA_SMEM>>>(
        xh, xl, w1h, w1l, nullptr, qkv_buf, 3072, 1024);

    // 3) V row sums
    {
        dim3 g1(32, 16);
        vsum_partial<<<g1, 64>>>();
        vsum_reduce<<<32, 64>>>();
    }

    // 4) banded attention -> bf16 hi/lo att
    band_attn<<<32 * 256, 256>>>(epoch);

    // 5) out = att @ proj_w^T + proj_b : 128x256 tiles (grid 128, ~0.9 waves)
    gemm_tc<<<dim3(1024 / 256, 4096 / 128), 256, GEMM_TC_SMEM>>>(
        ah, al, w2h, w2l, proj_b, (float*)d_out, 1024, 1024, 1);
    gemm_mma<<<dim3(1024 / 128, 4096 / 128), 256, GEMM_MMA_SMEM>>>(
        ah, al, w2h, w2l, proj_b, (float*)d_out, 1024, 1024);
}

// round 9
// speedup vs baseline: 1.1722x; 1.1722x over previous
#include <cuda_runtime.h>
#include <cuda_bf16.h>
#include <cstdint>
#include <math.h>

// ---------------- scratch (static device globals; no runtime alloc) ----------
__device__ float g_qkv[2 * 2048 * 3072];        // [B,N,3C] fp32
__device__ float g_vsum[32 * 64];
__device__ float g_vsum_p[32 * 16 * 64];
__device__ __nv_bfloat16 g_xh[4096 * 1024], g_xl[4096 * 1024];
__device__ __nv_bfloat16 g_w1h[3072 * 1024], g_w1l[3072 * 1024];
__device__ __nv_bfloat16 g_w2h[1024 * 1024], g_w2l[1024 * 1024];
__device__ __nv_bfloat16 g_ah[4096 * 1024], g_al[4096 * 1024];
__device__ int g_tc_ok;

// ---------------- helpers -----------------------------------------------------
__device__ __forceinline__ unsigned short bfbits(__nv_bfloat16 v) {
    return *reinterpret_cast<unsigned short*>(&v);
}

// ---------------- fp32 -> bf16 hi/lo split -----------------------------------
__global__ void split_kernel(const float* __restrict__ src,
                             __nv_bfloat16* __restrict__ hi,
                             __nv_bfloat16* __restrict__ lo, int n4) {
    int i = blockIdx.x * 256 + threadIdx.x;
    if (i >= n4) return;
    float4 v = reinterpret_cast<const float4*>(src)[i];
    float vv[4] = {v.x, v.y, v.z, v.w};
    unsigned short hb[4], lb[4];
    #pragma unroll
    for (int j = 0; j < 4; j++) {
        __nv_bfloat16 h = __float2bfloat16_rn(vv[j]);
        __nv_bfloat16 l = __float2bfloat16_rn(vv[j] - __bfloat162float(h));
        hb[j] = bfbits(h); lb[j] = bfbits(l);
    }
    reinterpret_cast<ushort4*>(hi)[i] = make_ushort4(hb[0], hb[1], hb[2], hb[3]);
    reinterpret_cast<ushort4*>(lo)[i] = make_ushort4(lb[0], lb[1], lb[2], lb[3]);
}

// =============================================================================
// Path A: tcgen05 GEMM, 128x128 tile, K-chunk 32, SW64, 3 stages, OCC=2
// =============================================================================
#define NST 3
#define TILE_B 8192                       // 128 rows * 64 B (SW64)
#define STAGE_B (4 * TILE_B)              // Ah, Al, Bh, Bl = 32 KB
#define GEMM_TC_SMEM (2048 + NST * STAGE_B)   // 100352 B -> 2 CTAs/SM

#if defined(__CUDA_ARCH__) && defined(__CUDA_ARCH_FEAT_SM103_ALL)
__device__ __forceinline__ uint32_t elect1() {
    uint32_t p;
    asm volatile("{\n\t.reg .pred p;\n\telect.sync _|p, 0xFFFFFFFF;\n\tselp.b32 %0,1,0,p;\n\t}"
                 : "=r"(p));
    return p;
}
__device__ __forceinline__ uint64_t make_desc_sw64(uint32_t addr) {
    // layout=SW64(4), version=1, SBO=32, LBO=1
    return ((uint64_t)4 << 61) | ((uint64_t)1 << 46) | ((uint64_t)32 << 32) |
           ((uint64_t)1 << 16) | (uint64_t)((addr >> 4) & 0x3FFF);
}
__device__ __forceinline__ void mma_f16_ss(uint32_t d, uint64_t a, uint64_t b,
                                           uint32_t idesc, uint32_t acc) {
    asm volatile(
        "{\n\t.reg .pred p;\n\tsetp.ne.u32 p, %4, 0;\n\t"
        "tcgen05.mma.cta_group::1.kind::f16 [%0], %1, %2, %3, {%5,%5,%5,%5}, p;\n\t}"
        :: "r"(d), "l"(a), "l"(b), "r"(idesc), "r"(acc), "r"(0u) : "memory");
}
#define MBAR_INIT(a, c) \
    asm volatile("mbarrier.init.shared.b64 [%0], %1;" :: "r"(a), "r"(c) : "memory")
#define MBAR_WAIT(a, ph) do {                                                   \
    uint32_t _done = 0;                                                         \
    while (!_done) {                                                            \
        asm volatile(                                                           \
            "{\n\t.reg .pred p;\n\t"                                            \
            "mbarrier.try_wait.parity.acquire.cta.shared::cta.b64 p, [%1], %2, 0x989680;\n\t" \
            "selp.b32 %0,1,0,p;\n\t}"                                           \
            : "=r"(_done) : "r"(a), "r"((uint32_t)(ph)) : "memory");            \
    }                                                                           \
} while (0)
#define TC_COMMIT(mb) \
    asm volatile("tcgen05.commit.cta_group::1.mbarrier::arrive::one.shared::cluster.b64 [%0];" \
                 :: "r"(mb) : "memory")
#define TC_LD_X32(r, addr)                                                      \
    asm volatile("tcgen05.ld.sync.aligned.32x32b.x32.b32 "                      \
        "{%0,%1,%2,%3,%4,%5,%6,%7,%8,%9,%10,%11,%12,%13,%14,%15,"              \
        "%16,%17,%18,%19,%20,%21,%22,%23,%24,%25,%26,%27,%28,%29,%30,%31}, [%32];" \
        : "=r"((r)[0]),"=r"((r)[1]),"=r"((r)[2]),"=r"((r)[3]),                  \
          "=r"((r)[4]),"=r"((r)[5]),"=r"((r)[6]),"=r"((r)[7]),                  \
          "=r"((r)[8]),"=r"((r)[9]),"=r"((r)[10]),"=r"((r)[11]),                \
          "=r"((r)[12]),"=r"((r)[13]),"=r"((r)[14]),"=r"((r)[15]),              \
          "=r"((r)[16]),"=r"((r)[17]),"=r"((r)[18]),"=r"((r)[19]),              \
          "=r"((r)[20]),"=r"((r)[21]),"=r"((r)[22]),"=r"((r)[23]),              \
          "=r"((r)[24]),"=r"((r)[25]),"=r"((r)[26]),"=r"((r)[27]),              \
          "=r"((r)[28]),"=r"((r)[29]),"=r"((r)[30]),"=r"((r)[31])               \
        : "r"(addr))
#endif

__global__ __launch_bounds__(128, 2)
void gemm_tc(const __nv_bfloat16* __restrict__ Ah_, const __nv_bfloat16* __restrict__ Al_,
             const __nv_bfloat16* __restrict__ Bh_, const __nv_bfloat16* __restrict__ Bl_,
             const float* __restrict__ bias, float* __restrict__ C, int N, int K) {
#if defined(__CUDA_ARCH__) && defined(__CUDA_ARCH_FEAT_SM103_ALL)
    extern __shared__ char smem[];
    const int tid = threadIdx.x;
    const int wid = tid >> 5, lane = tid & 31;
    if (tid == 0) g_tc_ok = 1;
    const int bm = blockIdx.y * 128, bn = blockIdx.x * 128;
    const uint32_t sbase = (uint32_t)__cvta_generic_to_shared(smem);
    const uint32_t tiles0 = (sbase + 1024 + 1023) & ~1023u;
    const uint32_t mbd0 = sbase + 64, mbfin = sbase + 128;

    if (tid == 0) {
        #pragma unroll
        for (int s = 0; s < NST; s++) MBAR_INIT(mbd0 + 8 * s, 1);
        MBAR_INIT(mbfin, 1);
    }
    if (wid == 0) {
        asm volatile("tcgen05.alloc.cta_group::1.sync.aligned.shared::cta.b32 [%0], %1;"
                     :: "r"(sbase), "r"(128u) : "memory");
    }
    __syncthreads();
    uint32_t tmem;
    asm volatile("ld.shared.b32 %0, [%1];" : "=r"(tmem) : "r"(sbase));

    const __nv_bfloat16* srcs[4] = {
        Ah_ + (size_t)bm * K, Al_ + (size_t)bm * K,
        Bh_ + (size_t)bn * K, Bl_ + (size_t)bn * K };

    auto load_stage = [&](int kt) {
        const uint32_t sb = tiles0 + (uint32_t)(kt % NST) * STAGE_B;
        const int k0 = kt * 32;
        #pragma unroll
        for (int i = 0; i < 16; i++) {
            const int u = tid + i * 128;            // 0..2047
            const int t = u >> 9, r = u & 511;
            const int row = r >> 2, c = r & 3;
            uint32_t off = (uint32_t)row * 64 + (uint32_t)c * 16;
            uint32_t sw = off ^ ((off >> 3) & 0x30);
            asm volatile("cp.async.cg.shared.global [%0], [%1], 16;"
                         :: "r"(sb + (uint32_t)t * TILE_B + sw),
                            "l"(srcs[t] + (size_t)row * K + k0 + c * 8));
        }
        asm volatile("cp.async.commit_group;");
    };

    const int nkt = K >> 5;                 // K/32
    const uint32_t idesc = 0x8200490u;      // f32 d, bf16 a/b, M=128, N=128

    load_stage(0);
    if (nkt > 1) load_stage(1);

    for (int kt = 0; kt < nkt; kt++) {
        if (kt + 2 < nkt) {
            if (kt >= 1) {   // stage (kt+2)%NST was used by chunk kt-1
                MBAR_WAIT(mbd0 + 8 * ((kt - 1) % NST), ((kt - 1) / NST) & 1);
            }
            load_stage(kt + 2);
            asm volatile("cp.async.wait_group 2;");
        } else {
            asm volatile("cp.async.wait_group 0;");
        }
        __syncthreads();

        if (wid == 0 && elect1()) {
            asm volatile("fence.proxy.async.shared::cta;" ::: "memory");
            const uint32_t sb = tiles0 + (uint32_t)(kt % NST) * STAGE_B;
            const uint64_t dAh = make_desc_sw64(sb);
            const uint64_t dAl = make_desc_sw64(sb + TILE_B);
            const uint64_t dBh = make_desc_sw64(sb + 2 * TILE_B);
            const uint64_t dBl = make_desc_sw64(sb + 3 * TILE_B);
            #pragma unroll
            for (int k = 0; k < 2; k++) {
                const uint64_t o = 2 * k;
                const uint32_t acc0 = (kt == 0 && k == 0) ? 0u : 1u;
                mma_f16_ss(tmem, dAh + o, dBh + o, idesc, acc0);
                mma_f16_ss(tmem, dAh + o, dBl + o, idesc, 1u);
                mma_f16_ss(tmem, dAl + o, dBh + o, idesc, 1u);
            }
            TC_COMMIT(mbd0 + 8 * (kt % NST));
            if (kt == nkt - 1) TC_COMMIT(mbfin);   // single-shot final marker
        }
    }

    MBAR_WAIT(mbfin, 0);
    asm volatile("tcgen05.fence::after_thread_sync;" ::: "memory");
    __syncthreads();

    // epilogue: 4 warps read subpartitions, 32 cols per pass
    {
        const int row = bm + wid * 32 + lane;
        float* Cr = C + (size_t)row * N + bn;
        #pragma unroll
        for (int g = 0; g < 4; g++) {
            uint32_t r[32];
            TC_LD_X32(r, tmem + g * 32);
            asm volatile("tcgen05.wait::ld.sync.aligned;" ::: "memory");
            #pragma unroll
            for (int j = 0; j < 32; j += 4) {
                float4 o;
                o.x = __uint_as_float(r[j + 0]);
                o.y = __uint_as_float(r[j + 1]);
                o.z = __uint_as_float(r[j + 2]);
                o.w = __uint_as_float(r[j + 3]);
                if (bias) {
                    const float4 b4 = *reinterpret_cast<const float4*>(bias + bn + g * 32 + j);
                    o.x += b4.x; o.y += b4.y; o.z += b4.z; o.w += b4.w;
                }
                *reinterpret_cast<float4*>(Cr + g * 32 + j) = o;
            }
        }
        asm volatile("tcgen05.fence::before_thread_sync;" ::: "memory");
    }
    __syncthreads();
    if (wid == 0) {
        asm volatile("tcgen05.relinquish_alloc_permit.cta_group::1.sync.aligned;");
        asm volatile("tcgen05.dealloc.cta_group::1.sync.aligned.b32 %0, %1;"
                     :: "r"(tmem), "r"(128u));
    }
#endif
}

// =============================================================================
// Path B: fallback — 3xBF16 mma.sync (plain compute_103 safe); skips if A ran
// =============================================================================
#define MSTRIDE 20
#define MTILE_U32 (128 * MSTRIDE)
#define GEMM_MMA_SMEM (8 * MTILE_U32 * 4)

__device__ __forceinline__ void mma_bf16(float* c, const uint32_t* a, const uint32_t* b) {
    asm volatile(
        "mma.sync.aligned.m16n8k16.row.col.f32.bf16.bf16.f32 "
        "{%0,%1,%2,%3}, {%4,%5,%6,%7}, {%8,%9}, {%0,%1,%2,%3};"
        : "+f"(c[0]), "+f"(c[1]), "+f"(c[2]), "+f"(c[3])
        : "r"(a[0]), "r"(a[1]), "r"(a[2]), "r"(a[3]), "r"(b[0]), "r"(b[1]));
}

__global__ __launch_bounds__(256)
void gemm_mma(const __nv_bfloat16* __restrict__ Ah_, const __nv_bfloat16* __restrict__ Al_,
              const __nv_bfloat16* __restrict__ Bh_, const __nv_bfloat16* __restrict__ Bl_,
              const float* __restrict__ bias, float* __restrict__ C, int N, int K) {
    if (*(volatile int*)&g_tc_ok) return;
    extern __shared__ uint32_t sm_u[];

    const int tid = threadIdx.x;
    const int lane = tid & 31;
    const int wid = tid >> 5;
    const int warp_m = wid & 1;
    const int warp_n = wid >> 1;
    const int bm = blockIdx.y * 128;
    const int bn = blockIdx.x * 128;
    const int gr = lane >> 2;
    const int gc = lane & 3;

    const __nv_bfloat16* srcs[4] = {
        Ah_ + (size_t)bm * K, Al_ + (size_t)bm * K,
        Bh_ + (size_t)bn * K, Bl_ + (size_t)bn * K };

    float acc[4][4][4];
    #pragma unroll
    for (int i = 0; i < 4; i++)
        #pragma unroll
        for (int j = 0; j < 4; j++)
            #pragma unroll
            for (int r = 0; r < 4; r++) acc[i][j][r] = 0.0f;

    auto load_stage = [&](int s, int k0) {
        #pragma unroll
        for (int i = 0; i < 8; i++) {
            const int cid = tid + i * 256;
            const int t = cid >> 9;
            const int c = cid & 511;
            const int row = c >> 2, c16 = c & 3;
            uint32_t daddr = (uint32_t)__cvta_generic_to_shared(
                sm_u + (s * 4 + t) * MTILE_U32 + row * MSTRIDE + c16 * 4);
            asm volatile("cp.async.ca.shared.global [%0], [%1], 16;"
                         :: "r"(daddr), "l"(srcs[t] + (size_t)row * K + k0 + c16 * 8));
        }
        asm volatile("cp.async.commit_group;");
    };

    const int nkt = K >> 5;
    load_stage(0, 0);

    for (int kt = 0; kt < nkt; kt++) {
        const int s = kt & 1;
        if (kt + 1 < nkt) {
            load_stage(s ^ 1, (kt + 1) * 32);
            asm volatile("cp.async.wait_group 1;");
        } else {
            asm volatile("cp.async.wait_group 0;");
        }
        __syncthreads();

        const uint32_t* Abh = sm_u + (s * 4 + 0) * MTILE_U32;
        const uint32_t* Abl = sm_u + (s * 4 + 1) * MTILE_U32;
        const uint32_t* Bbh = sm_u + (s * 4 + 2) * MTILE_U32;
        const uint32_t* Bbl = sm_u + (s * 4 + 3) * MTILE_U32;

        #pragma unroll
        for (int ks = 0; ks < 2; ks++) {
            const int kb = ks * 8;
            uint32_t ah[4][4], al[4][4];
            #pragma unroll
            for (int i = 0; i < 4; i++) {
                const int base = (warp_m * 64 + i * 16 + gr) * MSTRIDE + kb + gc;
                ah[i][0] = Abh[base];           ah[i][1] = Abh[base + 8 * MSTRIDE];
                ah[i][2] = Abh[base + 4];       ah[i][3] = Abh[base + 8 * MSTRIDE + 4];
                al[i][0] = Abl[base];           al[i][1] = Abl[base + 8 * MSTRIDE];
                al[i][2] = Abl[base + 4];       al[i][3] = Abl[base + 8 * MSTRIDE + 4];
            }
            uint32_t bh[4][2], bl[4][2];
            #pragma unroll
            for (int j = 0; j < 4; j++) {
                const int bb = (warp_n * 32 + j * 8 + gr) * MSTRIDE + kb + gc;
                bh[j][0] = Bbh[bb];  bh[j][1] = Bbh[bb + 4];
                bl[j][0] = Bbl[bb];  bl[j][1] = Bbl[bb + 4];
            }
            #pragma unroll
            for (int i = 0; i < 4; i++)
                #pragma unroll
                for (int j = 0; j < 4; j++) {
                    mma_bf16(acc[i][j], ah[i], bh[j]);
                    mma_bf16(acc[i][j], ah[i], bl[j]);
                    mma_bf16(acc[i][j], al[i], bh[j]);
                }
        }
        __syncthreads();
    }

    #pragma unroll
    for (int i = 0; i < 4; i++) {
        const int row0 = bm + warp_m * 64 + i * 16 + gr;
        #pragma unroll
        for (int j = 0; j < 4; j++) {
            const int col = bn + warp_n * 32 + j * 8 + gc * 2;
            float2 v0 = make_float2(acc[i][j][0], acc[i][j][1]);
            float2 v1 = make_float2(acc[i][j][2], acc[i][j][3]);
            if (bias) {
                const float b0 = bias[col], b1 = bias[col + 1];
                v0.x += b0; v0.y += b1; v1.x += b0; v1.y += b1;
            }
            *reinterpret_cast<float2*>(C + (size_t)row0 * N + col) = v0;
            *reinterpret_cast<float2*>(C + (size_t)(row0 + 8) * N + col) = v1;
        }
    }
}

// ---------------- V row-sum (2-stage) ----------------------------------------
__global__ void vsum_partial() {
    const int N = 2048, C3 = 3072, Dh = 64, H = 16;
    const int bh = blockIdx.x, s = blockIdx.y;
    const int b = bh / H, h = bh % H;
    const int dh = threadIdx.x;
    const float* base = g_qkv + (size_t)(b * N) * C3 + 2048 + h * Dh + dh;
    float acc = 0.0f;
    const int n0 = s * 128;
    for (int n = n0; n < n0 + 128; n++) acc += base[(size_t)n * C3];
    g_vsum_p[(bh * 16 + s) * Dh + dh] = acc;
}
__global__ void vsum_reduce() {
    const int Dh = 64;
    const int bh = blockIdx.x, dh = threadIdx.x;
    float acc = 0.0f;
    #pragma unroll
    for (int s = 0; s < 16; s++) acc += g_vsum_p[(bh * 16 + s) * Dh + dh];
    g_vsum[bh * Dh + dh] = acc;
}

// ---------------- banded attention: 8 queries/block share K/V rows in smem ---
__global__ __launch_bounds__(256)
void band_attn(const int* __restrict__ epoch_p) {
    const int N = 2048, H = 16, C3 = 3072;
    const int w = (*epoch_p < 15) ? 16 : 20;

    __shared__ float sK[48 * 64];
    __shared__ float sV[48 * 64];

    const int tid = threadIdx.x;
    const int g = blockIdx.x;
    const int n0 = (g & 255) * 8;
    const int bh = g >> 8;
    const int b = bh >> 4, h = bh & 15;

    const int lo = max(0, n0 - w);
    const int hi = min(N - 1, n0 + 7 + w);
    const int rows = hi - lo + 1;

    const float* base = g_qkv + (size_t)(b * N + lo) * C3 + 1024 + h * 64;
    for (int idx = tid; idx < rows * 16; idx += 256) {
        const int r = idx >> 4, c4 = (idx & 15) * 4;
        *reinterpret_cast<float4*>(&sK[r * 64 + c4]) =
            *reinterpret_cast<const float4*>(base + (size_t)r * C3 + c4);
        *reinterpret_cast<float4*>(&sV[r * 64 + c4]) =
            *reinterpret_cast<const float4*>(base + (size_t)r * C3 + 1024 + c4);
    }
    __syncthreads();

    const int wid = tid >> 5, lane = tid & 31;
    const int n = n0 + wid;

    const float* qp = g_qkv + (size_t)(b * N + n) * C3 + h * 64;
    const float q0 = qp[lane], q1 = qp[lane + 32];
    const float s0 = g_vsum[bh * 64 + lane];
    const float s1 = g_vsum[bh * 64 + lane + 32];

    const int m0 = max(0, n - w);
    const int m1 = min(N - 1, n + w);

    float Mx = -INFINITY, Z = 0.0f;
    float a0 = 0.0f, a1 = 0.0f, bv0 = 0.0f, bv1 = 0.0f;

    for (int m = m0; m <= m1; m++) {
        const int r = m - lo;
        const float k0 = sK[r * 64 + lane], k1 = sK[r * 64 + lane + 32];
        const float v0 = sV[r * 64 + lane], v1 = sV[r * 64 + lane + 32];

        float p = q0 * k0 + q1 * k1;
        p += __shfl_xor_sync(0xffffffffu, p, 16);
        p += __shfl_xor_sync(0xffffffffu, p, 8);
        p += __shfl_xor_sync(0xffffffffu, p, 4);
        p += __shfl_xor_sync(0xffffffffu, p, 2);
        p += __shfl_xor_sync(0xffffffffu, p, 1);
        const float l = p * 4.0f;   // scale = Dh // H = 4

        if (l > Mx) {
            const float f = __expf(Mx - l);
            Z *= f; a0 *= f; a1 *= f;
            Mx = l;
        }
        const float e = __expf(l - Mx);
        Z += e;
        a0 = fmaf(e, v0, a0);
        a1 = fmaf(e, v1, a1);
        bv0 += v0; bv1 += v1;
    }

    const float lm = 1e-9f;
    const float cu = __expf(lm - Mx);
    const int nband = m1 - m0 + 1;
    Z += (float)(N - nband) * cu;

    const float invZ = 1.0f / Z;
    const float o0 = (a0 + cu * (s0 - bv0)) * invZ;
    const float o1 = (a1 + cu * (s1 - bv1)) * invZ;

    const size_t idx = (size_t)(b * N + n) * 1024 + h * 64;
    __nv_bfloat16 h0 = __float2bfloat16_rn(o0);
    __nv_bfloat16 l0 = __float2bfloat16_rn(o0 - __bfloat162float(h0));
    __nv_bfloat16 h1 = __float2bfloat16_rn(o1);
    __nv_bfloat16 l1 = __float2bfloat16_rn(o1 - __bfloat162float(h1));
    g_ah[idx + lane] = h0;  g_al[idx + lane] = l0;
    g_ah[idx + lane + 32] = h1;  g_al[idx + lane + 32] = l1;
}

// ---------------- launcher ---------------------------------------------------
extern "C" void kernel_launch(void* const* d_in, const int* in_sizes, int n_in,
                              void* d_out, int out_size) {
    const float* x      = (const float*)d_in[0];
    const float* qkv_w  = (const float*)d_in[1];
    const float* proj_w = (const float*)d_in[2];
    const float* proj_b = (const float*)d_in[3];
    const int*   epoch  = (const int*)d_in[4];

    float* qkv_buf;
    __nv_bfloat16 *xh, *xl, *w1h, *w1l, *w2h, *w2l, *ah, *al;
    cudaGetSymbolAddress((void**)&qkv_buf, g_qkv);
    cudaGetSymbolAddress((void**)&xh, g_xh);   cudaGetSymbolAddress((void**)&xl, g_xl);
    cudaGetSymbolAddress((void**)&w1h, g_w1h); cudaGetSymbolAddress((void**)&w1l, g_w1l);
    cudaGetSymbolAddress((void**)&w2h, g_w2h); cudaGetSymbolAddress((void**)&w2l, g_w2l);
    cudaGetSymbolAddress((void**)&ah, g_ah);   cudaGetSymbolAddress((void**)&al, g_al);

    cudaFuncSetAttribute(gemm_tc, cudaFuncAttributeMaxDynamicSharedMemorySize, GEMM_TC_SMEM);
    cudaFuncSetAttribute(gemm_mma, cudaFuncAttributeMaxDynamicSharedMemorySize, GEMM_MMA_SMEM);

    // 1) split inputs to bf16 hi/lo
    {
        int n4 = 4096 * 1024 / 4;
        split_kernel<<<(n4 + 255) / 256, 256>>>(x, xh, xl, n4);
        n4 = 3072 * 1024 / 4;
        split_kernel<<<(n4 + 255) / 256, 256>>>(qkv_w, w1h, w1l, n4);
        n4 = 1024 * 1024 / 4;
        split_kernel<<<(n4 + 255) / 256, 256>>>(proj_w, w2h, w2l, n4);
    }

    // 2) qkv = x @ qkv_w^T : 128x128 tcgen05 tiles at occupancy 2
    gemm_tc<<<dim3(3072 / 128, 4096 / 128), 128, GEMM_TC_SMEM>>>(
        xh, xl, w1h, w1l, nullptr, qkv_buf, 3072, 1024);
    gemm_mma<<<dim3(3072 / 128, 4096 / 128), 256, GEMM_MMA_SMEM>>>(
        xh, xl, w1h, w1l, nullptr, qkv_buf, 3072, 1024);

    // 3) V row sums
    {
        dim3 g1(32, 16);
        vsum_partial<<<g1, 64>>>();
        vsum_reduce<<<32, 64>>>();
    }

    // 4) banded attention -> bf16 hi/lo att
    band_attn<<<32 * 256, 256>>>(epoch);

    // 5) out = att @ proj_w^T + proj_b
    gemm_tc<<<dim3(1024 / 128, 4096 / 128), 128, GEMM_TC_SMEM>>>(
        ah, al, w2h, w2l, proj_b, (float*)d_out, 1024, 1024);
    gemm_mma<<<dim3(1024 / 128, 4096 / 128), 256, GEMM_MMA_SMEM>>>(
        ah, al, w2h, w2l, proj_b, (float*)d_out, 1024, 1024);
}

// round 10
// speedup vs baseline: 1.4568x; 1.2428x over previous
#include <cuda_runtime.h>
#include <cuda_bf16.h>
#include <cstdint>
#include <math.h>

// ---------------- scratch (static device globals; no runtime alloc) ----------
__device__ float g_qkv[2 * 2048 * 3072];        // [B,N,3C] fp32
__device__ float g_vsum[32 * 64];
__device__ float g_vsum_p[32 * 16 * 64];
// packed tiled bf16 operands: tile(rt,kt) = 128 rows x 32 cols, SW64-swizzled,
// 8192 B contiguous; tile index = rt*(K/32)+kt
__device__ __nv_bfloat16 g_xh[4096 * 1024], g_xl[4096 * 1024];
__device__ __nv_bfloat16 g_w1h[3072 * 1024], g_w1l[3072 * 1024];
__device__ __nv_bfloat16 g_w2h[1024 * 1024], g_w2l[1024 * 1024];
__device__ __nv_bfloat16 g_ah[4096 * 1024], g_al[4096 * 1024];

__device__ __forceinline__ unsigned short bfbits(__nv_bfloat16 v) {
    return *reinterpret_cast<unsigned short*>(&v);
}

// ---------------- fp32 -> bf16 hi/lo split INTO packed tiled layout ----------
__global__ void split_pack(const float* __restrict__ src,
                           __nv_bfloat16* __restrict__ hi,
                           __nv_bfloat16* __restrict__ lo, int n4) {
    int i = blockIdx.x * 256 + threadIdx.x;
    if (i >= n4) return;
    const int r = i >> 8;               // row (K=1024 -> 256 float4 per row)
    const int c4 = (i & 255) << 2;      // col of first element
    float4 v = reinterpret_cast<const float4*>(src)[i];
    float vv[4] = {v.x, v.y, v.z, v.w};
    unsigned short hb[4], lb[4];
    #pragma unroll
    for (int j = 0; j < 4; j++) {
        __nv_bfloat16 h = __float2bfloat16_rn(vv[j]);
        __nv_bfloat16 l = __float2bfloat16_rn(vv[j] - __bfloat162float(h));
        hb[j] = bfbits(h); lb[j] = bfbits(l);
    }
    const int rt = r >> 7, rowin = r & 127;
    const int kt = c4 >> 5, colin = c4 & 31;
    uint32_t off = (uint32_t)rowin * 64 + (uint32_t)colin * 2;
    uint32_t sw = off ^ ((off >> 3) & 0x30);
    size_t dst = ((size_t)(rt * 32 + kt)) * 4096 + (sw >> 1);
    *reinterpret_cast<ushort4*>(hi + dst) = make_ushort4(hb[0], hb[1], hb[2], hb[3]);
    *reinterpret_cast<ushort4*>(lo + dst) = make_ushort4(lb[0], lb[1], lb[2], lb[3]);
}

// =============================================================================
// tcgen05 GEMM: 128x256 tile, K-chunk 32, packed tiles + cp.async.bulk (TMA),
// single control thread, 4-stage ring.
// =============================================================================
#define NSTG 4
#define STG_B 49152                       // Ah,Al (8K each) + Bh,Bl (16K each)
#define GEMM_TC_SMEM (2048 + NSTG * STG_B)   // 198656 B

#if defined(__CUDA_ARCH__) && defined(__CUDA_ARCH_FEAT_SM103_ALL)
__device__ __forceinline__ uint64_t make_desc_sw64(uint32_t addr) {
    // layout=SW64(4), version=1, SBO=32, LBO=1
    return ((uint64_t)4 << 61) | ((uint64_t)1 << 46) | ((uint64_t)32 << 32) |
           ((uint64_t)1 << 16) | (uint64_t)((addr >> 4) & 0x3FFF);
}
__device__ __forceinline__ void mma_f16_ss(uint32_t d, uint64_t a, uint64_t b,
                                           uint32_t idesc, uint32_t acc) {
    asm volatile(
        "{\n\t.reg .pred p;\n\tsetp.ne.u32 p, %4, 0;\n\t"
        "tcgen05.mma.cta_group::1.kind::f16 [%0], %1, %2, %3, {%5,%5,%5,%5}, p;\n\t}"
        :: "r"(d), "l"(a), "l"(b), "r"(idesc), "r"(acc), "r"(0u) : "memory");
}
__device__ __forceinline__ void bulk_g2s(uint32_t dst, const void* src,
                                         uint32_t bytes, uint32_t mbar) {
    asm volatile(
        "cp.async.bulk.shared::cluster.global.mbarrier::complete_tx::bytes "
        "[%0], [%1], %2, [%3];"
        :: "r"(dst), "l"(src), "r"(bytes), "r"(mbar) : "memory");
}
#define MBAR_INIT(a, c) \
    asm volatile("mbarrier.init.shared.b64 [%0], %1;" :: "r"(a), "r"(c) : "memory")
#define MBAR_EXPECT_TX(a, bytes) \
    asm volatile("mbarrier.arrive.expect_tx.shared.b64 _, [%0], %1;" \
                 :: "r"(a), "r"(bytes) : "memory")
#define MBAR_WAIT(a, ph) do {                                                   \
    uint32_t _done = 0;                                                         \
    while (!_done) {                                                            \
        asm volatile(                                                           \
            "{\n\t.reg .pred p;\n\t"                                            \
            "mbarrier.try_wait.parity.acquire.cta.shared::cta.b64 p, [%1], %2, 0x989680;\n\t" \
            "selp.b32 %0,1,0,p;\n\t}"                                           \
            : "=r"(_done) : "r"(a), "r"((uint32_t)(ph)) : "memory");            \
    }                                                                           \
} while (0)
#define TC_COMMIT(mb) \
    asm volatile("tcgen05.commit.cta_group::1.mbarrier::arrive::one.shared::cluster.b64 [%0];" \
                 :: "r"(mb) : "memory")
#define TC_LD_X32(r, addr)                                                      \
    asm volatile("tcgen05.ld.sync.aligned.32x32b.x32.b32 "                      \
        "{%0,%1,%2,%3,%4,%5,%6,%7,%8,%9,%10,%11,%12,%13,%14,%15,"              \
        "%16,%17,%18,%19,%20,%21,%22,%23,%24,%25,%26,%27,%28,%29,%30,%31}, [%32];" \
        : "=r"((r)[0]),"=r"((r)[1]),"=r"((r)[2]),"=r"((r)[3]),                  \
          "=r"((r)[4]),"=r"((r)[5]),"=r"((r)[6]),"=r"((r)[7]),                  \
          "=r"((r)[8]),"=r"((r)[9]),"=r"((r)[10]),"=r"((r)[11]),                \
          "=r"((r)[12]),"=r"((r)[13]),"=r"((r)[14]),"=r"((r)[15]),              \
          "=r"((r)[16]),"=r"((r)[17]),"=r"((r)[18]),"=r"((r)[19]),              \
          "=r"((r)[20]),"=r"((r)[21]),"=r"((r)[22]),"=r"((r)[23]),              \
          "=r"((r)[24]),"=r"((r)[25]),"=r"((r)[26]),"=r"((r)[27]),              \
          "=r"((r)[28]),"=r"((r)[29]),"=r"((r)[30]),"=r"((r)[31])               \
        : "r"(addr))
#endif

__global__ __launch_bounds__(128, 1)
void gemm_tc(const __nv_bfloat16* __restrict__ Ah_, const __nv_bfloat16* __restrict__ Al_,
             const __nv_bfloat16* __restrict__ Bh_, const __nv_bfloat16* __restrict__ Bl_,
             const float* __restrict__ bias, float* __restrict__ C, int N, int K) {
#if defined(__CUDA_ARCH__) && defined(__CUDA_ARCH_FEAT_SM103_ALL)
    extern __shared__ char smem[];
    const int tid = threadIdx.x;
    const int wid = tid >> 5, lane = tid & 31;
    const int bm = blockIdx.y * 128, bn = blockIdx.x * 256;
    const uint32_t sbase = (uint32_t)__cvta_generic_to_shared(smem);
    const uint32_t tiles0 = (sbase + 1024 + 1023) & ~1023u;
    const uint32_t full0 = sbase + 64, done0 = sbase + 128, mbfin = sbase + 192;

    if (tid == 0) {
        #pragma unroll
        for (int s = 0; s < NSTG; s++) { MBAR_INIT(full0 + 8 * s, 1); MBAR_INIT(done0 + 8 * s, 1); }
        MBAR_INIT(mbfin, 1);
    }
    if (wid == 0) {
        asm volatile("tcgen05.alloc.cta_group::1.sync.aligned.shared::cta.b32 [%0], %1;"
                     :: "r"(sbase), "r"(256u) : "memory");
    }
    __syncthreads();
    uint32_t tmem;
    asm volatile("ld.shared.b32 %0, [%1];" : "=r"(tmem) : "r"(sbase));

    const int nkt = K >> 5;                 // chunks of 32 cols
    const uint32_t idesc = 0x8400490u;      // f32 d, bf16 a/b, M=128, N=256

    if (tid == 0) {
        // tile bases (elements): A row-tile bm>>7 ; B row-tiles bn>>7, bn>>7+1
        const __nv_bfloat16* tAh = Ah_ + (size_t)(bm >> 7) * nkt * 4096;
        const __nv_bfloat16* tAl = Al_ + (size_t)(bm >> 7) * nkt * 4096;
        const __nv_bfloat16* tBh = Bh_ + (size_t)(bn >> 7) * nkt * 4096;
        const __nv_bfloat16* tBl = Bl_ + (size_t)(bn >> 7) * nkt * 4096;

        auto issue_loads = [&](int j) {
            const uint32_t sb = tiles0 + (uint32_t)(j & 3) * STG_B;
            const uint32_t mb = full0 + 8 * (j & 3);
            MBAR_EXPECT_TX(mb, (uint32_t)STG_B);
            bulk_g2s(sb,          tAh + (size_t)j * 4096,         8192, mb);
            bulk_g2s(sb + 8192,   tAl + (size_t)j * 4096,         8192, mb);
            bulk_g2s(sb + 16384,  tBh + (size_t)j * 4096,         8192, mb);
            bulk_g2s(sb + 24576,  tBh + (size_t)(nkt + j) * 4096, 8192, mb);
            bulk_g2s(sb + 32768,  tBl + (size_t)j * 4096,         8192, mb);
            bulk_g2s(sb + 40960,  tBl + (size_t)(nkt + j) * 4096, 8192, mb);
        };

        for (int j = 0; j < NSTG - 1 && j < nkt; j++) issue_loads(j);

        for (int kt = 0; kt < nkt; kt++) {
            const int s = kt & 3;
            MBAR_WAIT(full0 + 8 * s, (kt >> 2) & 1);
            const uint32_t sb = tiles0 + (uint32_t)s * STG_B;
            const uint64_t dAh = make_desc_sw64(sb);
            const uint64_t dAl = make_desc_sw64(sb + 8192);
            const uint64_t dBh = make_desc_sw64(sb + 16384);
            const uint64_t dBl = make_desc_sw64(sb + 32768);
            #pragma unroll
            for (int k = 0; k < 2; k++) {
                const uint64_t o = 2 * k;
                const uint32_t acc0 = (kt == 0 && k == 0) ? 0u : 1u;
                mma_f16_ss(tmem, dAh + o, dBh + o, idesc, acc0);
                mma_f16_ss(tmem, dAh + o, dBl + o, idesc, 1u);
                mma_f16_ss(tmem, dAl + o, dBh + o, idesc, 1u);
            }
            TC_COMMIT(done0 + 8 * s);
            const int j = kt + NSTG - 1;
            if (j < nkt) {
                if (kt >= 1) {   // stage (kt-1)&3 about to be reused
                    MBAR_WAIT(done0 + 8 * ((kt - 1) & 3), ((kt - 1) >> 2) & 1);
                }
                issue_loads(j);
            }
            if (kt == nkt - 1) TC_COMMIT(mbfin);
        }
    }

    MBAR_WAIT(mbfin, 0);
    asm volatile("tcgen05.fence::after_thread_sync;" ::: "memory");
    __syncthreads();

    // epilogue: 4 warps, 256 cols each row
    {
        const int row = bm + wid * 32 + lane;
        float* Cr = C + (size_t)row * N + bn;
        for (int g = 0; g < 8; g++) {
            uint32_t r[32];
            TC_LD_X32(r, tmem + g * 32);
            asm volatile("tcgen05.wait::ld.sync.aligned;" ::: "memory");
            #pragma unroll
            for (int j = 0; j < 32; j += 4) {
                float4 o;
                o.x = __uint_as_float(r[j + 0]);
                o.y = __uint_as_float(r[j + 1]);
                o.z = __uint_as_float(r[j + 2]);
                o.w = __uint_as_float(r[j + 3]);
                if (bias) {
                    const float4 b4 = *reinterpret_cast<const float4*>(bias + bn + g * 32 + j);
                    o.x += b4.x; o.y += b4.y; o.z += b4.z; o.w += b4.w;
                }
                *reinterpret_cast<float4*>(Cr + g * 32 + j) = o;
            }
        }
        asm volatile("tcgen05.fence::before_thread_sync;" ::: "memory");
    }
    __syncthreads();
    if (wid == 0) {
        asm volatile("tcgen05.relinquish_alloc_permit.cta_group::1.sync.aligned;");
        asm volatile("tcgen05.dealloc.cta_group::1.sync.aligned.b32 %0, %1;"
                     :: "r"(tmem), "r"(256u));
    }
#endif
}

// ---------------- V row-sum (2-stage) ----------------------------------------
__global__ void vsum_partial() {
    const int N = 2048, C3 = 3072, Dh = 64, H = 16;
    const int bh = blockIdx.x, s = blockIdx.y;
    const int b = bh / H, h = bh % H;
    const int dh = threadIdx.x;
    const float* base = g_qkv + (size_t)(b * N) * C3 + 2048 + h * Dh + dh;
    float acc = 0.0f;
    const int n0 = s * 128;
    for (int n = n0; n < n0 + 128; n++) acc += base[(size_t)n * C3];
    g_vsum_p[(bh * 16 + s) * Dh + dh] = acc;
}
__global__ void vsum_reduce() {
    const int Dh = 64;
    const int bh = blockIdx.x, dh = threadIdx.x;
    float acc = 0.0f;
    #pragma unroll
    for (int s = 0; s < 16; s++) acc += g_vsum_p[(bh * 16 + s) * Dh + dh];
    g_vsum[bh * Dh + dh] = acc;
}

// ---------------- banded attention: writes packed bf16 hi/lo -----------------
__global__ __launch_bounds__(256)
void band_attn(const int* __restrict__ epoch_p) {
    const int N = 2048, H = 16, C3 = 3072;
    const int w = (*epoch_p < 15) ? 16 : 20;

    __shared__ float sK[48 * 64];
    __shared__ float sV[48 * 64];

    const int tid = threadIdx.x;
    const int g = blockIdx.x;
    const int n0 = (g & 255) * 8;
    const int bh = g >> 8;
    const int b = bh >> 4, h = bh & 15;

    const int lo = max(0, n0 - w);
    const int hi = min(N - 1, n0 + 7 + w);
    const int rows = hi - lo + 1;

    const float* base = g_qkv + (size_t)(b * N + lo) * C3 + 1024 + h * 64;
    for (int idx = tid; idx < rows * 16; idx += 256) {
        const int r = idx >> 4, c4 = (idx & 15) * 4;
        *reinterpret_cast<float4*>(&sK[r * 64 + c4]) =
            *reinterpret_cast<const float4*>(base + (size_t)r * C3 + c4);
        *reinterpret_cast<float4*>(&sV[r * 64 + c4]) =
            *reinterpret_cast<const float4*>(base + (size_t)r * C3 + 1024 + c4);
    }
    __syncthreads();

    const int wid = tid >> 5, lane = tid & 31;
    const int n = n0 + wid;

    const float* qp = g_qkv + (size_t)(b * N + n) * C3 + h * 64;
    const float q0 = qp[lane], q1 = qp[lane + 32];
    const float s0 = g_vsum[bh * 64 + lane];
    const float s1 = g_vsum[bh * 64 + lane + 32];

    const int m0 = max(0, n - w);
    const int m1 = min(N - 1, n + w);

    float Mx = -INFINITY, Z = 0.0f;
    float a0 = 0.0f, a1 = 0.0f, bv0 = 0.0f, bv1 = 0.0f;

    for (int m = m0; m <= m1; m++) {
        const int r = m - lo;
        const float k0 = sK[r * 64 + lane], k1 = sK[r * 64 + lane + 32];
        const float v0 = sV[r * 64 + lane], v1 = sV[r * 64 + lane + 32];

        float p = q0 * k0 + q1 * k1;
        p += __shfl_xor_sync(0xffffffffu, p, 16);
        p += __shfl_xor_sync(0xffffffffu, p, 8);
        p += __shfl_xor_sync(0xffffffffu, p, 4);
        p += __shfl_xor_sync(0xffffffffu, p, 2);
        p += __shfl_xor_sync(0xffffffffu, p, 1);
        const float l = p * 4.0f;   // scale = Dh // H = 4

        if (l > Mx) {
            const float f = __expf(Mx - l);
            Z *= f; a0 *= f; a1 *= f;
            Mx = l;
        }
        const float e = __expf(l - Mx);
        Z += e;
        a0 = fmaf(e, v0, a0);
        a1 = fmaf(e, v1, a1);
        bv0 += v0; bv1 += v1;
    }

    const float lm = 1e-9f;
    const float cu = __expf(lm - Mx);
    const int nband = m1 - m0 + 1;
    Z += (float)(N - nband) * cu;

    const float invZ = 1.0f / Z;
    const float o0 = (a0 + cu * (s0 - bv0)) * invZ;
    const float o1 = (a1 + cu * (s1 - bv1)) * invZ;

    // packed tiled store: row r, cols h*64+lane and h*64+32+lane
    const int rr = b * N + n;
    const int rt = rr >> 7, rowin = rr & 127;
    uint32_t off = (uint32_t)rowin * 64 + (uint32_t)lane * 2;
    uint32_t sw = off ^ ((off >> 3) & 0x30);
    const size_t t0 = ((size_t)(rt * 32 + 2 * h)) * 4096 + (sw >> 1);
    const size_t t1 = ((size_t)(rt * 32 + 2 * h + 1)) * 4096 + (sw >> 1);

    __nv_bfloat16 h0 = __float2bfloat16_rn(o0);
    __nv_bfloat16 l0 = __float2bfloat16_rn(o0 - __bfloat162float(h0));
    __nv_bfloat16 h1 = __float2bfloat16_rn(o1);
    __nv_bfloat16 l1 = __float2bfloat16_rn(o1 - __bfloat162float(h1));
    g_ah[t0] = h0;  g_al[t0] = l0;
    g_ah[t1] = h1;  g_al[t1] = l1;
}

// ---------------- launcher ---------------------------------------------------
extern "C" void kernel_launch(void* const* d_in, const int* in_sizes, int n_in,
                              void* d_out, int out_size) {
    const float* x      = (const float*)d_in[0];
    const float* qkv_w  = (const float*)d_in[1];
    const float* proj_w = (const float*)d_in[2];
    const float* proj_b = (const float*)d_in[3];
    const int*   epoch  = (const int*)d_in[4];

    float* qkv_buf;
    __nv_bfloat16 *xh, *xl, *w1h, *w1l, *w2h, *w2l, *ah, *al;
    cudaGetSymbolAddress((void**)&qkv_buf, g_qkv);
    cudaGetSymbolAddress((void**)&xh, g_xh);   cudaGetSymbolAddress((void**)&xl, g_xl);
    cudaGetSymbolAddress((void**)&w1h, g_w1h); cudaGetSymbolAddress((void**)&w1l, g_w1l);
    cudaGetSymbolAddress((void**)&w2h, g_w2h); cudaGetSymbolAddress((void**)&w2l, g_w2l);
    cudaGetSymbolAddress((void**)&ah, g_ah);   cudaGetSymbolAddress((void**)&al, g_al);

    cudaFuncSetAttribute(gemm_tc, cudaFuncAttributeMaxDynamicSharedMemorySize, GEMM_TC_SMEM);

    // 1) split inputs to packed tiled bf16 hi/lo
    {
        int n4 = 4096 * 256;
        split_pack<<<(n4 + 255) / 256, 256>>>(x, xh, xl, n4);
        n4 = 3072 * 256;
        split_pack<<<(n4 + 255) / 256, 256>>>(qkv_w, w1h, w1l, n4);
        n4 = 1024 * 256;
        split_pack<<<(n4 + 255) / 256, 256>>>(proj_w, w2h, w2l, n4);
    }

    // 2) qkv = x @ qkv_w^T : 128x256 tiles, TMA bulk pipeline
    gemm_tc<<<dim3(3072 / 256, 4096 / 128), 128, GEMM_TC_SMEM>>>(
        xh, xl, w1h, w1l, nullptr, qkv_buf, 3072, 1024);

    // 3) V row sums
    {
        dim3 g1(32, 16);
        vsum_partial<<<g1, 64>>>();
        vsum_reduce<<<32, 64>>>();
    }

    // 4) banded attention -> packed bf16 hi/lo att
    band_attn<<<32 * 256, 256>>>(epoch);

    // 5) out = att @ proj_w^T + proj_b
    gemm_tc<<<dim3(1024 / 256, 4096 / 128), 128, GEMM_TC_SMEM>>>(
        ah, al, w2h, w2l, proj_b, (float*)d_out, 1024, 1024);
}

// round 11
// speedup vs baseline: 1.5258x; 1.0474x over previous
#include <cuda_runtime.h>
#include <cuda_bf16.h>
#include <cstdint>
#include <math.h>

// ---------------- scratch (static device globals; no runtime alloc) ----------
__device__ float g_qkv[2 * 2048 * 3072];        // [B,N,3C] fp32
__device__ float g_vsum[32 * 64];
__device__ float g_vsum_p[32 * 16 * 64];
// packed tiled bf16 operands: tile(rt,kt) = 128 rows x 32 cols, SW64-swizzled,
// 8192 B contiguous; tile index = rt*(K/32)+kt
__device__ __nv_bfloat16 g_xh[4096 * 1024], g_xl[4096 * 1024];
__device__ __nv_bfloat16 g_w1h[3072 * 1024], g_w1l[3072 * 1024];
__device__ __nv_bfloat16 g_w2h[1024 * 1024], g_w2l[1024 * 1024];
__device__ __nv_bfloat16 g_ah[4096 * 1024], g_al[4096 * 1024];

__device__ __forceinline__ unsigned short bfbits(__nv_bfloat16 v) {
    return *reinterpret_cast<unsigned short*>(&v);
}

// ---------------- fp32 -> bf16 hi/lo split INTO packed tiled layout ----------
__global__ void split_pack(const float* __restrict__ src,
                           __nv_bfloat16* __restrict__ hi,
                           __nv_bfloat16* __restrict__ lo, int n4) {
    int i = blockIdx.x * 256 + threadIdx.x;
    if (i >= n4) return;
    const int r = i >> 8;               // row (K=1024 -> 256 float4 per row)
    const int c4 = (i & 255) << 2;      // col of first element
    float4 v = reinterpret_cast<const float4*>(src)[i];
    float vv[4] = {v.x, v.y, v.z, v.w};
    unsigned short hb[4], lb[4];
    #pragma unroll
    for (int j = 0; j < 4; j++) {
        __nv_bfloat16 h = __float2bfloat16_rn(vv[j]);
        __nv_bfloat16 l = __float2bfloat16_rn(vv[j] - __bfloat162float(h));
        hb[j] = bfbits(h); lb[j] = bfbits(l);
    }
    const int rt = r >> 7, rowin = r & 127;
    const int kt = c4 >> 5, colin = c4 & 31;
    uint32_t off = (uint32_t)rowin * 64 + (uint32_t)colin * 2;
    uint32_t sw = off ^ ((off >> 3) & 0x30);
    size_t dst = ((size_t)(rt * 32 + kt)) * 4096 + (sw >> 1);
    *reinterpret_cast<ushort4*>(hi + dst) = make_ushort4(hb[0], hb[1], hb[2], hb[3]);
    *reinterpret_cast<ushort4*>(lo + dst) = make_ushort4(lb[0], lb[1], lb[2], lb[3]);
}

// =============================================================================
// tcgen05 cg2 GEMM: 2-CTA cluster computes 256x256 tile; K-chunk 32; packed
// tiles + cp.async.bulk; 5-stage ring; leader issues M=256 N=256 MMAs.
// =============================================================================
#define NSTG 5
#define STG_B 32768                       // Ah,Al,Bh,Bl @ 8 KB each
#define GEMM_TC_SMEM (2048 + NSTG * STG_B)   // 165888 B

#if defined(__CUDA_ARCH__) && defined(__CUDA_ARCH_FEAT_SM103_ALL)
__device__ __forceinline__ uint64_t make_desc_sw64(uint32_t addr) {
    // layout=SW64(4), version=1, SBO=32, LBO=1
    return ((uint64_t)4 << 61) | ((uint64_t)1 << 46) | ((uint64_t)32 << 32) |
           ((uint64_t)1 << 16) | (uint64_t)((addr >> 4) & 0x3FFF);
}
__device__ __forceinline__ void mma_f16_ss_cg2(uint32_t d, uint64_t a, uint64_t b,
                                               uint32_t idesc, uint32_t acc) {
    asm volatile(
        "{\n\t.reg .pred p;\n\tsetp.ne.u32 p, %4, 0;\n\t"
        "tcgen05.mma.cta_group::2.kind::f16 [%0], %1, %2, %3, "
        "{%5,%5,%5,%5,%5,%5,%5,%5}, p;\n\t}"
        :: "r"(d), "l"(a), "l"(b), "r"(idesc), "r"(acc), "r"(0u) : "memory");
}
__device__ __forceinline__ void bulk_g2s(uint32_t dst, const void* src,
                                         uint32_t bytes, uint32_t mbar) {
    asm volatile(
        "cp.async.bulk.shared::cluster.global.mbarrier::complete_tx::bytes "
        "[%0], [%1], %2, [%3];"
        :: "r"(dst), "l"(src), "r"(bytes), "r"(mbar) : "memory");
}
#define MBAR_INIT(a, c) \
    asm volatile("mbarrier.init.shared.b64 [%0], %1;" :: "r"(a), "r"(c) : "memory")
#define MBAR_EXPECT_TX(a, bytes) \
    asm volatile("mbarrier.arrive.expect_tx.shared.b64 _, [%0], %1;" \
                 :: "r"(a), "r"(bytes) : "memory")
#define MBAR_WAIT(a, ph) do {                                                   \
    uint32_t _done = 0;                                                         \
    while (!_done) {                                                            \
        asm volatile(                                                           \
            "{\n\t.reg .pred p;\n\t"                                            \
            "mbarrier.try_wait.parity.acquire.cta.shared::cta.b64 p, [%1], %2, 0x989680;\n\t" \
            "selp.b32 %0,1,0,p;\n\t}"                                           \
            : "=r"(_done) : "r"(a), "r"((uint32_t)(ph)) : "memory");            \
    }                                                                           \
} while (0)
#define MBAR_ARRIVE_RANK0(localaddr) \
    asm volatile( \
        "{\n\t.reg .b32 ra;\n\tmapa.shared::cluster.u32 ra, %0, 0;\n\t" \
        "mbarrier.arrive.shared::cluster.b64 _, [ra];\n\t}" \
        :: "r"(localaddr) : "memory")
#define TC_COMMIT_MC2(mb) \
    asm volatile("tcgen05.commit.cta_group::2.mbarrier::arrive::one.shared::cluster.multicast::cluster.b64 [%0], %1;" \
                 :: "r"(mb), "h"((unsigned short)0x3) : "memory")
#define TC_LD_X32(r, addr)                                                      \
    asm volatile("tcgen05.ld.sync.aligned.32x32b.x32.b32 "                      \
        "{%0,%1,%2,%3,%4,%5,%6,%7,%8,%9,%10,%11,%12,%13,%14,%15,"              \
        "%16,%17,%18,%19,%20,%21,%22,%23,%24,%25,%26,%27,%28,%29,%30,%31}, [%32];" \
        : "=r"((r)[0]),"=r"((r)[1]),"=r"((r)[2]),"=r"((r)[3]),                  \
          "=r"((r)[4]),"=r"((r)[5]),"=r"((r)[6]),"=r"((r)[7]),                  \
          "=r"((r)[8]),"=r"((r)[9]),"=r"((r)[10]),"=r"((r)[11]),                \
          "=r"((r)[12]),"=r"((r)[13]),"=r"((r)[14]),"=r"((r)[15]),              \
          "=r"((r)[16]),"=r"((r)[17]),"=r"((r)[18]),"=r"((r)[19]),              \
          "=r"((r)[20]),"=r"((r)[21]),"=r"((r)[22]),"=r"((r)[23]),              \
          "=r"((r)[24]),"=r"((r)[25]),"=r"((r)[26]),"=r"((r)[27]),              \
          "=r"((r)[28]),"=r"((r)[29]),"=r"((r)[30]),"=r"((r)[31])               \
        : "r"(addr))
#define CLUSTER_SYNC_() do { \
    asm volatile("barrier.cluster.arrive.aligned;" ::: "memory"); \
    asm volatile("barrier.cluster.wait.aligned;" ::: "memory"); \
} while (0)
#endif

__global__ __launch_bounds__(128, 1) __cluster_dims__(2, 1, 1)
void gemm_tc(const __nv_bfloat16* __restrict__ Ah_, const __nv_bfloat16* __restrict__ Al_,
             const __nv_bfloat16* __restrict__ Bh_, const __nv_bfloat16* __restrict__ Bl_,
             const float* __restrict__ bias, float* __restrict__ C, int N, int K) {
#if defined(__CUDA_ARCH__) && defined(__CUDA_ARCH_FEAT_SM103_ALL)
    extern __shared__ char smem[];
    const int tid = threadIdx.x;
    const int wid = tid >> 5, lane = tid & 31;
    const int rank = blockIdx.x & 1;                 // cluster rank (dim x = 2)
    const int bn = (blockIdx.x >> 1) * 256;
    const int bm = blockIdx.y * 256 + rank * 128;    // this CTA's 128 M-rows
    const uint32_t sbase = (uint32_t)__cvta_generic_to_shared(smem);
    const uint32_t tiles0 = (sbase + 1024 + 1023) & ~1023u;
    const uint32_t full0 = sbase + 64, done0 = sbase + 128;
    const uint32_t rdy0 = sbase + 192, mbfin = sbase + 256;

    if (tid == 0) {
        #pragma unroll
        for (int s = 0; s < NSTG; s++) {
            MBAR_INIT(full0 + 8 * s, 1);
            MBAR_INIT(done0 + 8 * s, 1);
            MBAR_INIT(rdy0 + 8 * s, 1);
        }
        MBAR_INIT(mbfin, 1);
    }
    if (wid == 0) {
        asm volatile("tcgen05.alloc.cta_group::2.sync.aligned.shared::cta.b32 [%0], %1;"
                     :: "r"(sbase), "r"(256u) : "memory");
    }
    __syncthreads();
    uint32_t tmem;
    asm volatile("ld.shared.b32 %0, [%1];" : "=r"(tmem) : "r"(sbase));

    // all barriers initialized in BOTH CTAs before any cross-CTA arrivals
    CLUSTER_SYNC_();

    const int nkt = K >> 5;                  // chunks of 32 K-cols
    const uint32_t idesc = 0x10400490u;      // f32 d, bf16 a/b, M=256, N=256

    if (tid == 0) {
        const int rtA = blockIdx.y * 2 + rank;             // A row-tile
        const int rtB = (blockIdx.x >> 1) * 2 + rank;      // this CTA's B half
        const __nv_bfloat16* tAh = Ah_ + (size_t)rtA * nkt * 4096;
        const __nv_bfloat16* tAl = Al_ + (size_t)rtA * nkt * 4096;
        const __nv_bfloat16* tBh = Bh_ + (size_t)rtB * nkt * 4096;
        const __nv_bfloat16* tBl = Bl_ + (size_t)rtB * nkt * 4096;

        auto issue_loads = [&](int j) {
            const int s = j % NSTG;
            const uint32_t sb = tiles0 + (uint32_t)s * STG_B;
            const uint32_t mb = full0 + 8 * s;
            MBAR_EXPECT_TX(mb, (uint32_t)STG_B);
            bulk_g2s(sb,          tAh + (size_t)j * 4096, 8192, mb);
            bulk_g2s(sb + 8192,   tAl + (size_t)j * 4096, 8192, mb);
            bulk_g2s(sb + 16384,  tBh + (size_t)j * 4096, 8192, mb);
            bulk_g2s(sb + 24576,  tBl + (size_t)j * 4096, 8192, mb);
        };

        for (int j = 0; j < NSTG - 1 && j < nkt; j++) issue_loads(j);

        for (int kt = 0; kt < nkt; kt++) {
            const int s = kt % NSTG;
            const int ph = (kt / NSTG) & 1;
            MBAR_WAIT(full0 + 8 * s, ph);
            if (rank == 0) {
                // wait peer's half of the stage, then run the pair MMA
                MBAR_WAIT(rdy0 + 8 * s, ph);
                const uint32_t sb = tiles0 + (uint32_t)s * STG_B;
                const uint64_t dAh = make_desc_sw64(sb);
                const uint64_t dAl = make_desc_sw64(sb + 8192);
                const uint64_t dBh = make_desc_sw64(sb + 16384);
                const uint64_t dBl = make_desc_sw64(sb + 24576);
                #pragma unroll
                for (int k = 0; k < 2; k++) {
                    const uint64_t o = 2 * k;
                    const uint32_t acc0 = (kt == 0 && k == 0) ? 0u : 1u;
                    mma_f16_ss_cg2(tmem, dAh + o, dBh + o, idesc, acc0);
                    mma_f16_ss_cg2(tmem, dAh + o, dBl + o, idesc, 1u);
                    mma_f16_ss_cg2(tmem, dAl + o, dBh + o, idesc, 1u);
                }
                TC_COMMIT_MC2(done0 + 8 * s);
                if (kt == nkt - 1) TC_COMMIT_MC2(mbfin);
            } else {
                MBAR_ARRIVE_RANK0(rdy0 + 8 * s);
            }
            const int j = kt + NSTG - 1;
            if (j < nkt) {
                if (kt >= 1) {   // stage (kt-1)%NSTG about to be reused
                    MBAR_WAIT(done0 + 8 * ((kt - 1) % NSTG), ((kt - 1) / NSTG) & 1);
                }
                issue_loads(j);
            }
        }
    }

    MBAR_WAIT(mbfin, 0);
    asm volatile("tcgen05.fence::after_thread_sync;" ::: "memory");
    __syncthreads();

    // epilogue: each CTA reads its own 128 lanes x 256 cols
    {
        const int row = bm + wid * 32 + lane;
        float* Cr = C + (size_t)row * N + bn;
        for (int g = 0; g < 8; g++) {
            uint32_t r[32];
            TC_LD_X32(r, tmem + g * 32);
            asm volatile("tcgen05.wait::ld.sync.aligned;" ::: "memory");
            #pragma unroll
            for (int j = 0; j < 32; j += 4) {
                float4 o;
                o.x = __uint_as_float(r[j + 0]);
                o.y = __uint_as_float(r[j + 1]);
                o.z = __uint_as_float(r[j + 2]);
                o.w = __uint_as_float(r[j + 3]);
                if (bias) {
                    const float4 b4 = *reinterpret_cast<const float4*>(bias + bn + g * 32 + j);
                    o.x += b4.x; o.y += b4.y; o.z += b4.z; o.w += b4.w;
                }
                *reinterpret_cast<float4*>(Cr + g * 32 + j) = o;
            }
        }
        asm volatile("tcgen05.fence::before_thread_sync;" ::: "memory");
    }
    __syncthreads();
    if (wid == 0) {
        asm volatile("tcgen05.relinquish_alloc_permit.cta_group::2.sync.aligned;");
        asm volatile("tcgen05.dealloc.cta_group::2.sync.aligned.b32 %0, %1;"
                     :: "r"(tmem), "r"(256u));
    }
    CLUSTER_SYNC_();
#endif
}

// ---------------- V row-sum (2-stage) ----------------------------------------
__global__ void vsum_partial() {
    const int N = 2048, C3 = 3072, Dh = 64, H = 16;
    const int bh = blockIdx.x, s = blockIdx.y;
    const int b = bh / H, h = bh % H;
    const int dh = threadIdx.x;
    const float* base = g_qkv + (size_t)(b * N) * C3 + 2048 + h * Dh + dh;
    float acc = 0.0f;
    const int n0 = s * 128;
    for (int n = n0; n < n0 + 128; n++) acc += base[(size_t)n * C3];
    g_vsum_p[(bh * 16 + s) * Dh + dh] = acc;
}
__global__ void vsum_reduce() {
    const int Dh = 64;
    const int bh = blockIdx.x, dh = threadIdx.x;
    float acc = 0.0f;
    #pragma unroll
    for (int s = 0; s < 16; s++) acc += g_vsum_p[(bh * 16 + s) * Dh + dh];
    g_vsum[bh * Dh + dh] = acc;
}

// ---------------- banded attention: writes packed bf16 hi/lo -----------------
__global__ __launch_bounds__(256)
void band_attn(const int* __restrict__ epoch_p) {
    const int N = 2048, H = 16, C3 = 3072;
    const int w = (*epoch_p < 15) ? 16 : 20;

    __shared__ float sK[48 * 64];
    __shared__ float sV[48 * 64];

    const int tid = threadIdx.x;
    const int g = blockIdx.x;
    const int n0 = (g & 255) * 8;
    const int bh = g >> 8;
    const int b = bh >> 4, h = bh & 15;

    const int lo = max(0, n0 - w);
    const int hi = min(N - 1, n0 + 7 + w);
    const int rows = hi - lo + 1;

    const float* base = g_qkv + (size_t)(b * N + lo) * C3 + 1024 + h * 64;
    for (int idx = tid; idx < rows * 16; idx += 256) {
        const int r = idx >> 4, c4 = (idx & 15) * 4;
        *reinterpret_cast<float4*>(&sK[r * 64 + c4]) =
            *reinterpret_cast<const float4*>(base + (size_t)r * C3 + c4);
        *reinterpret_cast<float4*>(&sV[r * 64 + c4]) =
            *reinterpret_cast<const float4*>(base + (size_t)r * C3 + 1024 + c4);
    }
    __syncthreads();

    const int wid = tid >> 5, lane = tid & 31;
    const int n = n0 + wid;

    const float* qp = g_qkv + (size_t)(b * N + n) * C3 + h * 64;
    const float q0 = qp[lane], q1 = qp[lane + 32];
    const float s0 = g_vsum[bh * 64 + lane];
    const float s1 = g_vsum[bh * 64 + lane + 32];

    const int m0 = max(0, n - w);
    const int m1 = min(N - 1, n + w);

    float Mx = -INFINITY, Z = 0.0f;
    float a0 = 0.0f, a1 = 0.0f, bv0 = 0.0f, bv1 = 0.0f;

    for (int m = m0; m <= m1; m++) {
        const int r = m - lo;
        const float k0 = sK[r * 64 + lane], k1 = sK[r * 64 + lane + 32];
        const float v0 = sV[r * 64 + lane], v1 = sV[r * 64 + lane + 32];

        float p = q0 * k0 + q1 * k1;
        p += __shfl_xor_sync(0xffffffffu, p, 16);
        p += __shfl_xor_sync(0xffffffffu, p, 8);
        p += __shfl_xor_sync(0xffffffffu, p, 4);
        p += __shfl_xor_sync(0xffffffffu, p, 2);
        p += __shfl_xor_sync(0xffffffffu, p, 1);
        const float l = p * 4.0f;   // scale = Dh // H = 4

        if (l > Mx) {
            const float f = __expf(Mx - l);
            Z *= f; a0 *= f; a1 *= f;
            Mx = l;
        }
        const float e = __expf(l - Mx);
        Z += e;
        a0 = fmaf(e, v0, a0);
        a1 = fmaf(e, v1, a1);
        bv0 += v0; bv1 += v1;
    }

    const float lm = 1e-9f;
    const float cu = __expf(lm - Mx);
    const int nband = m1 - m0 + 1;
    Z += (float)(N - nband) * cu;

    const float invZ = 1.0f / Z;
    const float o0 = (a0 + cu * (s0 - bv0)) * invZ;
    const float o1 = (a1 + cu * (s1 - bv1)) * invZ;

    // packed tiled store: row rr, cols h*64+lane and h*64+32+lane
    const int rr = b * N + n;
    const int rt = rr >> 7, rowin = rr & 127;
    uint32_t off = (uint32_t)rowin * 64 + (uint32_t)lane * 2;
    uint32_t sw = off ^ ((off >> 3) & 0x30);
    const size_t t0 = ((size_t)(rt * 32 + 2 * h)) * 4096 + (sw >> 1);
    const size_t t1 = ((size_t)(rt * 32 + 2 * h + 1)) * 4096 + (sw >> 1);

    __nv_bfloat16 h0 = __float2bfloat16_rn(o0);
    __nv_bfloat16 l0 = __float2bfloat16_rn(o0 - __bfloat162float(h0));
    __nv_bfloat16 h1 = __float2bfloat16_rn(o1);
    __nv_bfloat16 l1 = __float2bfloat16_rn(o1 - __bfloat162float(h1));
    g_ah[t0] = h0;  g_al[t0] = l0;
    g_ah[t1] = h1;  g_al[t1] = l1;
}

// ---------------- launcher ---------------------------------------------------
extern "C" void kernel_launch(void* const* d_in, const int* in_sizes, int n_in,
                              void* d_out, int out_size) {
    const float* x      = (const float*)d_in[0];
    const float* qkv_w  = (const float*)d_in[1];
    const float* proj_w = (const float*)d_in[2];
    const float* proj_b = (const float*)d_in[3];
    const int*   epoch  = (const int*)d_in[4];

    float* qkv_buf;
    __nv_bfloat16 *xh, *xl, *w1h, *w1l, *w2h, *w2l, *ah, *al;
    cudaGetSymbolAddress((void**)&qkv_buf, g_qkv);
    cudaGetSymbolAddress((void**)&xh, g_xh);   cudaGetSymbolAddress((void**)&xl, g_xl);
    cudaGetSymbolAddress((void**)&w1h, g_w1h); cudaGetSymbolAddress((void**)&w1l, g_w1l);
    cudaGetSymbolAddress((void**)&w2h, g_w2h); cudaGetSymbolAddress((void**)&w2l, g_w2l);
    cudaGetSymbolAddress((void**)&ah, g_ah);   cudaGetSymbolAddress((void**)&al, g_al);

    cudaFuncSetAttribute(gemm_tc, cudaFuncAttributeMaxDynamicSharedMemorySize, GEMM_TC_SMEM);

    // 1) split inputs to packed tiled bf16 hi/lo
    {
        int n4 = 4096 * 256;
        split_pack<<<(n4 + 255) / 256, 256>>>(x, xh, xl, n4);
        n4 = 3072 * 256;
        split_pack<<<(n4 + 255) / 256, 256>>>(qkv_w, w1h, w1l, n4);
        n4 = 1024 * 256;
        split_pack<<<(n4 + 255) / 256, 256>>>(proj_w, w2h, w2l, n4);
    }

    // 2) qkv = x @ qkv_w^T : 2-CTA clusters, 256x256 per cluster
    gemm_tc<<<dim3(2 * (3072 / 256), 4096 / 256), 128, GEMM_TC_SMEM>>>(
        xh, xl, w1h, w1l, nullptr, qkv_buf, 3072, 1024);

    // 3) V row sums
    {
        dim3 g1(32, 16);
        vsum_partial<<<g1, 64>>>();
        vsum_reduce<<<32, 64>>>();
    }

    // 4) banded attention -> packed bf16 hi/lo att
    band_attn<<<32 * 256, 256>>>(epoch);

    // 5) out = att @ proj_w^T + proj_b
    gemm_tc<<<dim3(2 * (1024 / 256), 4096 / 256), 128, GEMM_TC_SMEM>>>(
        ah, al, w2h, w2l, proj_b, (float*)d_out, 1024, 1024);
}

// round 12
// speedup vs baseline: 1.6289x; 1.0676x over previous
#include <cuda_runtime.h>
#include <cuda_bf16.h>
#include <cstdint>
#include <math.h>

// ---------------- scratch (static device globals; no runtime alloc) ----------
__device__ float g_qkv[2 * 2048 * 3072];        // [B,N,3C] fp32
__device__ float g_vsum[32 * 64];
__device__ float g_vsum_p[32 * 16 * 64];
// packed tiled bf16 operands: tile(rt,kt) = 128 rows x 32 cols, SW64-swizzled,
// 8192 B contiguous; tile index = rt*(K/32)+kt
__device__ __nv_bfloat16 g_xh[4096 * 1024], g_xl[4096 * 1024];
__device__ __nv_bfloat16 g_w1h[3072 * 1024], g_w1l[3072 * 1024];
__device__ __nv_bfloat16 g_w2h[1024 * 1024], g_w2l[1024 * 1024];
__device__ __nv_bfloat16 g_ah[4096 * 1024], g_al[4096 * 1024];

__device__ __forceinline__ unsigned short bfbits(__nv_bfloat16 v) {
    return *reinterpret_cast<unsigned short*>(&v);
}

// ---------------- fp32 -> bf16 hi/lo split INTO packed tiled layout ----------
__global__ void split_pack(const float* __restrict__ src,
                           __nv_bfloat16* __restrict__ hi,
                           __nv_bfloat16* __restrict__ lo, int n4) {
    int i = blockIdx.x * 256 + threadIdx.x;
    if (i >= n4) return;
    const int r = i >> 8;
    const int c4 = (i & 255) << 2;
    float4 v = reinterpret_cast<const float4*>(src)[i];
    float vv[4] = {v.x, v.y, v.z, v.w};
    unsigned short hb[4], lb[4];
    #pragma unroll
    for (int j = 0; j < 4; j++) {
        __nv_bfloat16 h = __float2bfloat16_rn(vv[j]);
        __nv_bfloat16 l = __float2bfloat16_rn(vv[j] - __bfloat162float(h));
        hb[j] = bfbits(h); lb[j] = bfbits(l);
    }
    const int rt = r >> 7, rowin = r & 127;
    const int kt = c4 >> 5, colin = c4 & 31;
    uint32_t off = (uint32_t)rowin * 64 + (uint32_t)colin * 2;
    uint32_t sw = off ^ ((off >> 3) & 0x30);
    size_t dst = ((size_t)(rt * 32 + kt)) * 4096 + (sw >> 1);
    *reinterpret_cast<ushort4*>(hi + dst) = make_ushort4(hb[0], hb[1], hb[2], hb[3]);
    *reinterpret_cast<ushort4*>(lo + dst) = make_ushort4(lb[0], lb[1], lb[2], lb[3]);
}

// =============================================================================
// tcgen05 cg2 GEMM: 2-CTA cluster computes 256x256 tile; K-chunk 32; packed
// tiles + cp.async.bulk; 5-stage ring; WARP-SPECIALIZED control:
//   rank0 warp0 thread: MMA consumer (never waits on done)
//   rank1 warp0 thread: forwards full[s] -> rank0 rdy[s]
//   warp1 thread (both): load producer (absorbs commit latency)
// =============================================================================
#define NSTG 5
#define STG_B 32768
#define GEMM_TC_SMEM (2048 + NSTG * STG_B)

#if defined(__CUDA_ARCH__) && defined(__CUDA_ARCH_FEAT_SM103_ALL)
__device__ __forceinline__ uint32_t elect1() {
    uint32_t p;
    asm volatile("{\n\t.reg .pred p;\n\telect.sync _|p, 0xFFFFFFFF;\n\tselp.b32 %0,1,0,p;\n\t}"
                 : "=r"(p));
    return p;
}
__device__ __forceinline__ uint64_t make_desc_sw64(uint32_t addr) {
    return ((uint64_t)4 << 61) | ((uint64_t)1 << 46) | ((uint64_t)32 << 32) |
           ((uint64_t)1 << 16) | (uint64_t)((addr >> 4) & 0x3FFF);
}
__device__ __forceinline__ void mma_f16_ss_cg2(uint32_t d, uint64_t a, uint64_t b,
                                               uint32_t idesc, uint32_t acc) {
    asm volatile(
        "{\n\t.reg .pred p;\n\tsetp.ne.u32 p, %4, 0;\n\t"
        "tcgen05.mma.cta_group::2.kind::f16 [%0], %1, %2, %3, "
        "{%5,%5,%5,%5,%5,%5,%5,%5}, p;\n\t}"
        :: "r"(d), "l"(a), "l"(b), "r"(idesc), "r"(acc), "r"(0u) : "memory");
}
__device__ __forceinline__ void bulk_g2s(uint32_t dst, const void* src,
                                         uint32_t bytes, uint32_t mbar) {
    asm volatile(
        "cp.async.bulk.shared::cluster.global.mbarrier::complete_tx::bytes "
        "[%0], [%1], %2, [%3];"
        :: "r"(dst), "l"(src), "r"(bytes), "r"(mbar) : "memory");
}
#define MBAR_INIT(a, c) \
    asm volatile("mbarrier.init.shared.b64 [%0], %1;" :: "r"(a), "r"(c) : "memory")
#define MBAR_EXPECT_TX(a, bytes) \
    asm volatile("mbarrier.arrive.expect_tx.shared.b64 _, [%0], %1;" \
                 :: "r"(a), "r"(bytes) : "memory")
#define MBAR_WAIT(a, ph) do {                                                   \
    uint32_t _done = 0;                                                         \
    while (!_done) {                                                            \
        asm volatile(                                                           \
            "{\n\t.reg .pred p;\n\t"                                            \
            "mbarrier.try_wait.parity.acquire.cta.shared::cta.b64 p, [%1], %2, 0x989680;\n\t" \
            "selp.b32 %0,1,0,p;\n\t}"                                           \
            : "=r"(_done) : "r"(a), "r"((uint32_t)(ph)) : "memory");            \
    }                                                                           \
} while (0)
#define MBAR_ARRIVE_RANK0(localaddr) \
    asm volatile( \
        "{\n\t.reg .b32 ra;\n\tmapa.shared::cluster.u32 ra, %0, 0;\n\t" \
        "mbarrier.arrive.shared::cluster.b64 _, [ra];\n\t}" \
        :: "r"(localaddr) : "memory")
#define TC_COMMIT_MC2(mb) \
    asm volatile("tcgen05.commit.cta_group::2.mbarrier::arrive::one.shared::cluster.multicast::cluster.b64 [%0], %1;" \
                 :: "r"(mb), "h"((unsigned short)0x3) : "memory")
#define TC_LD_X32(r, addr)                                                      \
    asm volatile("tcgen05.ld.sync.aligned.32x32b.x32.b32 "                      \
        "{%0,%1,%2,%3,%4,%5,%6,%7,%8,%9,%10,%11,%12,%13,%14,%15,"              \
        "%16,%17,%18,%19,%20,%21,%22,%23,%24,%25,%26,%27,%28,%29,%30,%31}, [%32];" \
        : "=r"((r)[0]),"=r"((r)[1]),"=r"((r)[2]),"=r"((r)[3]),                  \
          "=r"((r)[4]),"=r"((r)[5]),"=r"((r)[6]),"=r"((r)[7]),                  \
          "=r"((r)[8]),"=r"((r)[9]),"=r"((r)[10]),"=r"((r)[11]),                \
          "=r"((r)[12]),"=r"((r)[13]),"=r"((r)[14]),"=r"((r)[15]),              \
          "=r"((r)[16]),"=r"((r)[17]),"=r"((r)[18]),"=r"((r)[19]),              \
          "=r"((r)[20]),"=r"((r)[21]),"=r"((r)[22]),"=r"((r)[23]),              \
          "=r"((r)[24]),"=r"((r)[25]),"=r"((r)[26]),"=r"((r)[27]),              \
          "=r"((r)[28]),"=r"((r)[29]),"=r"((r)[30]),"=r"((r)[31])               \
        : "r"(addr))
#define CLUSTER_SYNC_() do { \
    asm volatile("barrier.cluster.arrive.aligned;" ::: "memory"); \
    asm volatile("barrier.cluster.wait.aligned;" ::: "memory"); \
} while (0)
#endif

__global__ __launch_bounds__(128, 1) __cluster_dims__(2, 1, 1)
void gemm_tc(const __nv_bfloat16* __restrict__ Ah_, const __nv_bfloat16* __restrict__ Al_,
             const __nv_bfloat16* __restrict__ Bh_, const __nv_bfloat16* __restrict__ Bl_,
             const float* __restrict__ bias, float* __restrict__ C, int N, int K) {
#if defined(__CUDA_ARCH__) && defined(__CUDA_ARCH_FEAT_SM103_ALL)
    extern __shared__ char smem[];
    const int tid = threadIdx.x;
    const int wid = tid >> 5, lane = tid & 31;
    const int rank = blockIdx.x & 1;
    const int bn = (blockIdx.x >> 1) * 256;
    const int bm = blockIdx.y * 256 + rank * 128;
    const uint32_t sbase = (uint32_t)__cvta_generic_to_shared(smem);
    const uint32_t tiles0 = (sbase + 1024 + 1023) & ~1023u;
    const uint32_t full0 = sbase + 64, done0 = sbase + 128;
    const uint32_t rdy0 = sbase + 192, mbfin = sbase + 256;

    if (tid == 0) {
        #pragma unroll
        for (int s = 0; s < NSTG; s++) {
            MBAR_INIT(full0 + 8 * s, 1);
            MBAR_INIT(done0 + 8 * s, 1);
            MBAR_INIT(rdy0 + 8 * s, 1);
        }
        MBAR_INIT(mbfin, 1);
    }
    if (wid == 0) {
        asm volatile("tcgen05.alloc.cta_group::2.sync.aligned.shared::cta.b32 [%0], %1;"
                     :: "r"(sbase), "r"(256u) : "memory");
    }
    __syncthreads();
    uint32_t tmem;
    asm volatile("ld.shared.b32 %0, [%1];" : "=r"(tmem) : "r"(sbase));

    CLUSTER_SYNC_();

    const int nkt = K >> 5;
    const uint32_t idesc = 0x10400490u;      // f32 d, bf16 a/b, M=256, N=256

    if (wid == 1 && elect1()) {
        // ---------------- producer (both ranks): streams the ring -------------
        const int rtA = blockIdx.y * 2 + rank;
        const int rtB = (blockIdx.x >> 1) * 2 + rank;
        const __nv_bfloat16* tAh = Ah_ + (size_t)rtA * nkt * 4096;
        const __nv_bfloat16* tAl = Al_ + (size_t)rtA * nkt * 4096;
        const __nv_bfloat16* tBh = Bh_ + (size_t)rtB * nkt * 4096;
        const __nv_bfloat16* tBl = Bl_ + (size_t)rtB * nkt * 4096;
        for (int j = 0; j < nkt; j++) {
            const int s = j % NSTG;
            if (j >= NSTG) {
                MBAR_WAIT(done0 + 8 * s, ((j / NSTG) - 1) & 1);
            }
            const uint32_t sb = tiles0 + (uint32_t)s * STG_B;
            const uint32_t mb = full0 + 8 * s;
            MBAR_EXPECT_TX(mb, (uint32_t)STG_B);
            bulk_g2s(sb,          tAh + (size_t)j * 4096, 8192, mb);
            bulk_g2s(sb + 8192,   tAl + (size_t)j * 4096, 8192, mb);
            bulk_g2s(sb + 16384,  tBh + (size_t)j * 4096, 8192, mb);
            bulk_g2s(sb + 24576,  tBl + (size_t)j * 4096, 8192, mb);
        }
    } else if (wid == 0 && elect1()) {
        if (rank == 0) {
            // ---------------- consumer: MMA stream, never waits on done -------
            for (int kt = 0; kt < nkt; kt++) {
                const int s = kt % NSTG;
                const int ph = (kt / NSTG) & 1;
                MBAR_WAIT(full0 + 8 * s, ph);
                MBAR_WAIT(rdy0 + 8 * s, ph);
                const uint32_t sb = tiles0 + (uint32_t)s * STG_B;
                const uint64_t dAh = make_desc_sw64(sb);
                const uint64_t dAl = make_desc_sw64(sb + 8192);
                const uint64_t dBh = make_desc_sw64(sb + 16384);
                const uint64_t dBl = make_desc_sw64(sb + 24576);
                #pragma unroll
                for (int k = 0; k < 2; k++) {
                    const uint64_t o = 2 * k;
                    const uint32_t acc0 = (kt == 0 && k == 0) ? 0u : 1u;
                    mma_f16_ss_cg2(tmem, dAh + o, dBh + o, idesc, acc0);
                    mma_f16_ss_cg2(tmem, dAh + o, dBl + o, idesc, 1u);
                    mma_f16_ss_cg2(tmem, dAl + o, dBh + o, idesc, 1u);
                }
                TC_COMMIT_MC2(done0 + 8 * s);
                if (kt == nkt - 1) TC_COMMIT_MC2(mbfin);
            }
        } else {
            // ---------------- rank1: forward full[s] -> rank0 rdy[s] ----------
            for (int kt = 0; kt < nkt; kt++) {
                const int s = kt % NSTG;
                const int ph = (kt / NSTG) & 1;
                MBAR_WAIT(full0 + 8 * s, ph);
                MBAR_ARRIVE_RANK0(rdy0 + 8 * s);
            }
        }
    }

    MBAR_WAIT(mbfin, 0);
    asm volatile("tcgen05.fence::after_thread_sync;" ::: "memory");
    __syncthreads();

    // epilogue: each CTA reads its own 128 lanes x 256 cols
    {
        const int row = bm + wid * 32 + lane;
        float* Cr = C + (size_t)row * N + bn;
        for (int g = 0; g < 8; g++) {
            uint32_t r[32];
            TC_LD_X32(r, tmem + g * 32);
            asm volatile("tcgen05.wait::ld.sync.aligned;" ::: "memory");
            #pragma unroll
            for (int j = 0; j < 32; j += 4) {
                float4 o;
                o.x = __uint_as_float(r[j + 0]);
                o.y = __uint_as_float(r[j + 1]);
                o.z = __uint_as_float(r[j + 2]);
                o.w = __uint_as_float(r[j + 3]);
                if (bias) {
                    const float4 b4 = *reinterpret_cast<const float4*>(bias + bn + g * 32 + j);
                    o.x += b4.x; o.y += b4.y; o.z += b4.z; o.w += b4.w;
                }
                *reinterpret_cast<float4*>(Cr + g * 32 + j) = o;
            }
        }
        asm volatile("tcgen05.fence::before_thread_sync;" ::: "memory");
    }
    __syncthreads();
    if (wid == 0) {
        asm volatile("tcgen05.relinquish_alloc_permit.cta_group::2.sync.aligned;");
        asm volatile("tcgen05.dealloc.cta_group::2.sync.aligned.b32 %0, %1;"
                     :: "r"(tmem), "r"(256u));
    }
    CLUSTER_SYNC_();
#endif
}

// ---------------- V row-sum (2-stage) ----------------------------------------
__global__ void vsum_partial() {
    const int N = 2048, C3 = 3072, Dh = 64, H = 16;
    const int bh = blockIdx.x, s = blockIdx.y;
    const int b = bh / H, h = bh % H;
    const int dh = threadIdx.x;
    const float* base = g_qkv + (size_t)(b * N) * C3 + 2048 + h * Dh + dh;
    float acc = 0.0f;
    const int n0 = s * 128;
    for (int n = n0; n < n0 + 128; n++) acc += base[(size_t)n * C3];
    g_vsum_p[(bh * 16 + s) * Dh + dh] = acc;
}
__global__ void vsum_reduce() {
    const int Dh = 64;
    const int bh = blockIdx.x, dh = threadIdx.x;
    float acc = 0.0f;
    #pragma unroll
    for (int s = 0; s < 16; s++) acc += g_vsum_p[(bh * 16 + s) * Dh + dh];
    g_vsum[bh * Dh + dh] = acc;
}

// ---------------- banded attention: writes packed bf16 hi/lo -----------------
__global__ __launch_bounds__(256)
void band_attn(const int* __restrict__ epoch_p) {
    const int N = 2048, H = 16, C3 = 3072;
    const int w = (*epoch_p < 15) ? 16 : 20;

    __shared__ float sK[48 * 64];
    __shared__ float sV[48 * 64];

    const int tid = threadIdx.x;
    const int g = blockIdx.x;
    const int n0 = (g & 255) * 8;
    const int bh = g >> 8;
    const int b = bh >> 4, h = bh & 15;

    const int lo = max(0, n0 - w);
    const int hi = min(N - 1, n0 + 7 + w);
    const int rows = hi - lo + 1;

    const float* base = g_qkv + (size_t)(b * N + lo) * C3 + 1024 + h * 64;
    for (int idx = tid; idx < rows * 16; idx += 256) {
        const int r = idx >> 4, c4 = (idx & 15) * 4;
        *reinterpret_cast<float4*>(&sK[r * 64 + c4]) =
            *reinterpret_cast<const float4*>(base + (size_t)r * C3 + c4);
        *reinterpret_cast<float4*>(&sV[r * 64 + c4]) =
            *reinterpret_cast<const float4*>(base + (size_t)r * C3 + 1024 + c4);
    }
    __syncthreads();

    const int wid = tid >> 5, lane = tid & 31;
    const int n = n0 + wid;

    const float* qp = g_qkv + (size_t)(b * N + n) * C3 + h * 64;
    const float q0 = qp[lane], q1 = qp[lane + 32];
    const float s0 = g_vsum[bh * 64 + lane];
    const float s1 = g_vsum[bh * 64 + lane + 32];

    const int m0 = max(0, n - w);
    const int m1 = min(N - 1, n + w);

    float Mx = -INFINITY, Z = 0.0f;
    float a0 = 0.0f, a1 = 0.0f, bv0 = 0.0f, bv1 = 0.0f;

    for (int m = m0; m <= m1; m++) {
        const int r = m - lo;
        const float k0 = sK[r * 64 + lane], k1 = sK[r * 64 + lane + 32];
        const float v0 = sV[r * 64 + lane], v1 = sV[r * 64 + lane + 32];

        float p = q0 * k0 + q1 * k1;
        p += __shfl_xor_sync(0xffffffffu, p, 16);
        p += __shfl_xor_sync(0xffffffffu, p, 8);
        p += __shfl_xor_sync(0xffffffffu, p, 4);
        p += __shfl_xor_sync(0xffffffffu, p, 2);
        p += __shfl_xor_sync(0xffffffffu, p, 1);
        const float l = p * 4.0f;   // scale = Dh // H = 4

        if (l > Mx) {
            const float f = __expf(Mx - l);
            Z *= f; a0 *= f; a1 *= f;
            Mx = l;
        }
        const float e = __expf(l - Mx);
        Z += e;
        a0 = fmaf(e, v0, a0);
        a1 = fmaf(e, v1, a1);
        bv0 += v0; bv1 += v1;
    }

    const float lm = 1e-9f;
    const float cu = __expf(lm - Mx);
    const int nband = m1 - m0 + 1;
    Z += (float)(N - nband) * cu;

    const float invZ = 1.0f / Z;
    const float o0 = (a0 + cu * (s0 - bv0)) * invZ;
    const float o1 = (a1 + cu * (s1 - bv1)) * invZ;

    const int rr = b * N + n;
    const int rt = rr >> 7, rowin = rr & 127;
    uint32_t off = (uint32_t)rowin * 64 + (uint32_t)lane * 2;
    uint32_t sw = off ^ ((off >> 3) & 0x30);
    const size_t t0 = ((size_t)(rt * 32 + 2 * h)) * 4096 + (sw >> 1);
    const size_t t1 = ((size_t)(rt * 32 + 2 * h + 1)) * 4096 + (sw >> 1);

    __nv_bfloat16 h0 = __float2bfloat16_rn(o0);
    __nv_bfloat16 l0 = __float2bfloat16_rn(o0 - __bfloat162float(h0));
    __nv_bfloat16 h1 = __float2bfloat16_rn(o1);
    __nv_bfloat16 l1 = __float2bfloat16_rn(o1 - __bfloat162float(h1));
    g_ah[t0] = h0;  g_al[t0] = l0;
    g_ah[t1] = h1;  g_al[t1] = l1;
}

// ---------------- launcher ---------------------------------------------------
extern "C" void kernel_launch(void* const* d_in, const int* in_sizes, int n_in,
                              void* d_out, int out_size) {
    const float* x      = (const float*)d_in[0];
    const float* qkv_w  = (const float*)d_in[1];
    const float* proj_w = (const float*)d_in[2];
    const float* proj_b = (const float*)d_in[3];
    const int*   epoch  = (const int*)d_in[4];

    float* qkv_buf;
    __nv_bfloat16 *xh, *xl, *w1h, *w1l, *w2h, *w2l, *ah, *al;
    cudaGetSymbolAddress((void**)&qkv_buf, g_qkv);
    cudaGetSymbolAddress((void**)&xh, g_xh);   cudaGetSymbolAddress((void**)&xl, g_xl);
    cudaGetSymbolAddress((void**)&w1h, g_w1h); cudaGetSymbolAddress((void**)&w1l, g_w1l);
    cudaGetSymbolAddress((void**)&w2h, g_w2h); cudaGetSymbolAddress((void**)&w2l, g_w2l);
    cudaGetSymbolAddress((void**)&ah, g_ah);   cudaGetSymbolAddress((void**)&al, g_al);

    cudaFuncSetAttribute(gemm_tc, cudaFuncAttributeMaxDynamicSharedMemorySize, GEMM_TC_SMEM);

    // 1) split inputs to packed tiled bf16 hi/lo
    {
        int n4 = 4096 * 256;
        split_pack<<<(n4 + 255) / 256, 256>>>(x, xh, xl, n4);
        n4 = 3072 * 256;
        split_pack<<<(n4 + 255) / 256, 256>>>(qkv_w, w1h, w1l, n4);
        n4 = 1024 * 256;
        split_pack<<<(n4 + 255) / 256, 256>>>(proj_w, w2h, w2l, n4);
    }

    // 2) qkv = x @ qkv_w^T : 2-CTA clusters, 256x256 per cluster
    gemm_tc<<<dim3(2 * (3072 / 256), 4096 / 256), 128, GEMM_TC_SMEM>>>(
        xh, xl, w1h, w1l, nullptr, qkv_buf, 3072, 1024);

    // 3) V row sums
    {
        dim3 g1(32, 16);
        vsum_partial<<<g1, 64>>>();
        vsum_reduce<<<32, 64>>>();
    }

    // 4) banded attention -> packed bf16 hi/lo att
    band_attn<<<32 * 256, 256>>>(epoch);

    // 5) out = att @ proj_w^T + proj_b
    gemm_tc<<<dim3(2 * (1024 / 256), 4096 / 256), 128, GEMM_TC_SMEM>>>(
        ah, al, w2h, w2l, proj_b, (float*)d_out, 1024, 1024);
}